// round 13
// baseline (speedup 1.0000x reference)
#include <cuda_runtime.h>
#include <cuda_fp16.h>
#include <cstdint>

#define DEV_INLINE __device__ __forceinline__

constexpr int Bb = 64, Tt = 96, Ff = 2048, Hh = 2048, Gg = 4 * Hh;
constexpr int M1 = Tt * Bb;                 // 6144

constexpr int OUT_H = 0;
constexpr int OUT_C = OUT_H + Tt * Bb * 2;
constexpr int OUT_U = OUT_C + Tt * Bb * 2;
constexpr int OUT_W = OUT_U + Tt * Bb;

__device__ __half g_featT[M1 * Ff];
__device__ __half g_wih[Gg * Ff];        // permuted rows
__device__ __half g_whh[Gg * Hh];        // permuted rows
__device__ __half g_xg[(size_t)M1 * Gg]; // permuted cols, fp16
__device__ float  g_chist[(size_t)M1 * Hh];
__device__ float  g_hhist[(size_t)M1 * Hh];
__device__ __half g_h16[2][Bb * Hh];     // double buffer (parity by t)
__device__ float  g_gumbel[Tt * Bb * 2];
__device__ float  g_bias[Gg];            // permuted

// ---------- threefry2x32 gumbel, key=(0,42), partitionable counter scheme ----------
DEV_INLINE uint32_t rotl32(uint32_t x, int d) { return (x << d) | (x >> (32 - d)); }
DEV_INLINE void tfr(uint32_t& x0, uint32_t& x1, int r) { x0 += x1; x1 = rotl32(x1, r); x1 ^= x0; }

DEV_INLINE float bits_to_gumbel(uint32_t bits) {
    float u0 = __uint_as_float((bits >> 9) | 0x3f800000u) - 1.0f;
    const float tiny = 1.1754943508222875e-38f;
    float u = fmaxf(u0 * (1.0f - tiny) + tiny, tiny);
    return -logf(-logf(u));
}

__global__ void gumbel_kernel(float* __restrict__ out) {
    int i = blockIdx.x * blockDim.x + threadIdx.x;
    if (i >= Tt * Bb * 2) return;
    uint32_t x0 = 0u, x1 = (uint32_t)i;
    const uint32_t k0 = 0u, k1 = 42u, k2 = 0u ^ 42u ^ 0x1BD11BDAu;
    x0 += k0; x1 += k1;
    tfr(x0,x1,13); tfr(x0,x1,15); tfr(x0,x1,26); tfr(x0,x1,6);
    x0 += k1; x1 += k2 + 1u;
    tfr(x0,x1,17); tfr(x0,x1,29); tfr(x0,x1,16); tfr(x0,x1,24);
    x0 += k2; x1 += k0 + 2u;
    tfr(x0,x1,13); tfr(x0,x1,15); tfr(x0,x1,26); tfr(x0,x1,6);
    x0 += k0; x1 += k1 + 3u;
    tfr(x0,x1,17); tfr(x0,x1,29); tfr(x0,x1,16); tfr(x0,x1,24);
    x0 += k1; x1 += k2 + 4u;
    tfr(x0,x1,13); tfr(x0,x1,15); tfr(x0,x1,26); tfr(x0,x1,6);
    x0 += k2; x1 += k0 + 5u;
    out[i] = bits_to_gumbel(x0 ^ x1);
}

// ---------- fp32 -> fp16 prep ----------
DEV_INLINE void h4store(float4 v, __half* o) {
    __half2* o2 = reinterpret_cast<__half2*>(o);
    o2[0] = __floats2half2_rn(v.x, v.y);
    o2[1] = __floats2half2_rn(v.z, v.w);
}

__global__ void perm_h16_kernel(const float* __restrict__ in, __half* __restrict__ o, int K) {
    int i = blockIdx.x * blockDim.x + threadIdx.x;
    if (i >= Gg * K / 4) return;
    int e = i * 4;
    int r = e / K, k = e % K;
    int orig = ((r & 3) << 11) + (r >> 2);
    float4 v = *reinterpret_cast<const float4*>(in + (size_t)orig * K + k);
    h4store(v, o + (size_t)e);
}

__global__ void feat_prep_kernel(const float* __restrict__ feat, __half* __restrict__ o) {
    int i = blockIdx.x * blockDim.x + threadIdx.x;
    if (i >= (M1 * Ff) / 4) return;
    int e = i * 4, m = e >> 11, f = e & 2047, b = m & 63, t = m >> 6;
    float4 v = *reinterpret_cast<const float4*>(feat + ((size_t)b * Tt + t) * Ff + f);
    h4store(v, o + (size_t)e);
}

__global__ void bias_perm_kernel(const float* __restrict__ a, const float* __restrict__ b,
                                 float* __restrict__ o) {
    int r = blockIdx.x * blockDim.x + threadIdx.x;
    if (r >= Gg) return;
    int orig = ((r & 3) << 11) + (r >> 2);
    o[r] = a[orig] + b[orig];
}

// ---------- mma + cp.async helpers ----------
DEV_INLINE void mma16816h(float c[4], const uint32_t a[4], const uint32_t b[2]) {
    asm volatile(
        "mma.sync.aligned.m16n8k16.row.col.f32.f16.f16.f32 "
        "{%0,%1,%2,%3}, {%4,%5,%6,%7}, {%8,%9}, {%0,%1,%2,%3};\n"
        : "+f"(c[0]), "+f"(c[1]), "+f"(c[2]), "+f"(c[3])
        : "r"(a[0]), "r"(a[1]), "r"(a[2]), "r"(a[3]), "r"(b[0]), "r"(b[1]));
}

DEV_INLINE void cp_async16(__half* smem_ptr, const __half* gptr) {
    uint32_t s = (uint32_t)__cvta_generic_to_shared(smem_ptr);
    asm volatile("cp.async.cg.shared.global [%0], [%1], 16;\n" :: "r"(s), "l"(gptr));
}
DEV_INLINE void cp_commit() { asm volatile("cp.async.commit_group;\n" ::: "memory"); }
template <int N> DEV_INLINE void cp_wait() { asm volatile("cp.async.wait_group %0;\n" :: "n"(N) : "memory"); }

// ---------- pipelined fp16 GEMM (input GEMM, chunked over M), fp16 out + fp32 bias ----------
template <int BM, int BN, int BK, int STAGES, int WROWS, int WCOLS, int WM, int WN>
__global__ void __launch_bounds__(WROWS * WCOLS * 32, 1)
gemm_pipe_kernel(const __half* __restrict__ A, const __half* __restrict__ B,
                 const float* __restrict__ addVec,
                 __half* __restrict__ Cout, int N, int K) {
    constexpr int NT = WROWS * WCOLS * 32;
    constexpr int LD = BK + 8, LD32 = LD / 2;
    constexpr int MI = WM / 16, NI = WN / 8;
    constexpr int A_ELE = BM * LD, B_ELE = BN * LD;
    constexpr int STAGE_ELE = A_ELE + B_ELE;

    extern __shared__ __half smem_g[];

    const int tid = threadIdx.x, wid = tid >> 5, lane = tid & 31;
    const int wrow = wid / WCOLS, wcol = wid % WCOLS;
    const int gl = lane >> 2, tig = lane & 3;
    const int bm = blockIdx.y * BM, bn = blockIdx.x * BN;
    const int KT = K / BK;

    float acc[MI][NI][4];
#pragma unroll
    for (int mi = 0; mi < MI; mi++)
#pragma unroll
        for (int ni = 0; ni < NI; ni++)
#pragma unroll
            for (int q = 0; q < 4; q++) acc[mi][ni][q] = 0.0f;

    auto load_stage = [&](int stg, int kt) {
        __half* sA = smem_g + stg * STAGE_ELE;
        __half* sB = sA + A_ELE;
        int k0 = kt * BK;
        for (int c = tid; c < BM * BK / 8; c += NT) {
            int r = c / (BK / 8), cc = (c % (BK / 8)) * 8;
            cp_async16(&sA[r * LD + cc], A + (size_t)(bm + r) * K + k0 + cc);
        }
        for (int c = tid; c < BN * BK / 8; c += NT) {
            int r = c / (BK / 8), cc = (c % (BK / 8)) * 8;
            cp_async16(&sB[r * LD + cc], B + (size_t)(bn + r) * K + k0 + cc);
        }
    };

#pragma unroll
    for (int s = 0; s < STAGES - 1; s++) {
        if (s < KT) load_stage(s, s);
        cp_commit();
    }

    for (int kt = 0; kt < KT; kt++) {
        cp_wait<STAGES - 2>();
        __syncthreads();
        int nk = kt + STAGES - 1;
        if (nk < KT) load_stage(nk % STAGES, nk);
        cp_commit();

        int stg = kt % STAGES;
        const uint32_t* A32 = reinterpret_cast<const uint32_t*>(smem_g + stg * STAGE_ELE);
        const uint32_t* B32 = A32 + A_ELE / 2;

#pragma unroll
        for (int ks = 0; ks < BK / 16; ks++) {
            uint32_t ah[MI][4];
#pragma unroll
            for (int mi = 0; mi < MI; mi++) {
                int r = wrow * WM + mi * 16 + gl;
                int p0 = r * LD32 + ks * 8 + tig, p1 = (r + 8) * LD32 + ks * 8 + tig;
                ah[mi][0] = A32[p0]; ah[mi][1] = A32[p1];
                ah[mi][2] = A32[p0 + 4]; ah[mi][3] = A32[p1 + 4];
            }
#pragma unroll
            for (int ni = 0; ni < NI; ni++) {
                int r = wcol * WN + ni * 8 + gl;
                int p = r * LD32 + ks * 8 + tig;
                uint32_t bh[2] = {B32[p], B32[p + 4]};
#pragma unroll
                for (int mi = 0; mi < MI; mi++) mma16816h(acc[mi][ni], ah[mi], bh);
            }
        }
    }

#pragma unroll
    for (int mi = 0; mi < MI; mi++) {
        int r0 = bm + wrow * WM + mi * 16 + gl, r1 = r0 + 8;
#pragma unroll
        for (int ni = 0; ni < NI; ni++) {
            int cb = bn + wcol * WN + ni * 8 + 2 * tig;
            float2 av = *reinterpret_cast<const float2*>(addVec + cb);
            __half2 h0 = __floats2half2_rn(acc[mi][ni][0] + av.x, acc[mi][ni][1] + av.y);
            __half2 h1 = __floats2half2_rn(acc[mi][ni][2] + av.x, acc[mi][ni][3] + av.y);
            *reinterpret_cast<__half2*>(Cout + (size_t)r0 * N + cb) = h0;
            *reinterpret_cast<__half2*>(Cout + (size_t)r1 * N + cb) = h1;
        }
    }
}

// ---------- fused step: gates GEMM (fp16) + LSTM (128 thr, 2x2 warps, MI=2 NI=4) ----------
constexpr int SBK = 64, SSTG = 3;
constexpr int SLD = SBK + 8, SLD32 = SLD / 2;
constexpr int S_AELE = 64 * SLD;                       // 4608 halves
constexpr int S_STAGE = 2 * S_AELE;                    // 9216 halves
constexpr int SMEM_STEP = SSTG * S_STAGE * 2;          // 55296 B
constexpr int SCLD = 68;                               // staging ld (floats)

__global__ void __launch_bounds__(128, 1)
step_fused_kernel(const __half* __restrict__ Hc, const __half* __restrict__ Wp,
                  const __half* __restrict__ xg_t,     // [64][Gg] permuted cols, fp16
                  const float* __restrict__ c_prev,
                  float* __restrict__ c_out, float* __restrict__ h_out,
                  __half* __restrict__ h16_o, int first) {
    constexpr int MI = 2, NI = 4;
    extern __shared__ __half smem_s[];

    const int tid = threadIdx.x, wid = tid >> 5, lane = tid & 31;
    const int wrow = wid >> 1, wcol = wid & 1;
    const int gl = lane >> 2, tig = lane & 3;
    const int bn = blockIdx.x * 64;
    constexpr int KT = Hh / SBK;   // 32

    float acc[MI][NI][4];
#pragma unroll
    for (int mi = 0; mi < MI; mi++)
#pragma unroll
        for (int ni = 0; ni < NI; ni++)
#pragma unroll
            for (int q = 0; q < 4; q++) acc[mi][ni][q] = 0.0f;

    if (!first) {
        auto load_stage = [&](int stg, int kt) {
            __half* sA = smem_s + stg * S_STAGE;
            __half* sB = sA + S_AELE;
            int k0 = kt * SBK;
            for (int c = tid; c < 64 * SBK / 8; c += 128) {
                int r = c >> 3, cc = (c & 7) * 8;
                cp_async16(&sA[r * SLD + cc], Hc + (size_t)r * Hh + k0 + cc);
                cp_async16(&sB[r * SLD + cc], Wp + (size_t)(bn + r) * Hh + k0 + cc);
            }
        };

#pragma unroll
        for (int s = 0; s < SSTG - 1; s++) { load_stage(s, s); cp_commit(); }

        for (int kt = 0; kt < KT; kt++) {
            cp_wait<SSTG - 2>();
            __syncthreads();
            int nk = kt + SSTG - 1;
            if (nk < KT) load_stage(nk % SSTG, nk);
            cp_commit();

            int stg = kt % SSTG;
            const uint32_t* A32 = reinterpret_cast<const uint32_t*>(smem_s + stg * S_STAGE);
            const uint32_t* B32 = A32 + S_AELE / 2;

#pragma unroll
            for (int ks = 0; ks < SBK / 16; ks++) {
                uint32_t ah[MI][4];
#pragma unroll
                for (int mi = 0; mi < MI; mi++) {
                    int r = wrow * 32 + mi * 16 + gl;
                    int p0 = r * SLD32 + ks * 8 + tig, p1 = (r + 8) * SLD32 + ks * 8 + tig;
                    ah[mi][0] = A32[p0]; ah[mi][1] = A32[p1];
                    ah[mi][2] = A32[p0 + 4]; ah[mi][3] = A32[p1 + 4];
                }
#pragma unroll
                for (int ni = 0; ni < NI; ni++) {
                    int r = wcol * 32 + ni * 8 + gl;
                    int p = r * SLD32 + ks * 8 + tig;
                    uint32_t bh[2] = {B32[p], B32[p + 4]};
#pragma unroll
                    for (int mi = 0; mi < MI; mi++) mma16816h(acc[mi][ni], ah[mi], bh);
                }
            }
        }
        cp_wait<0>();
    }
    __syncthreads();

    // stage gates = acc + xg (fp16) into smem
    float* sC = reinterpret_cast<float*>(smem_s);   // [64][SCLD]
#pragma unroll
    for (int mi = 0; mi < MI; mi++) {
        int r0 = wrow * 32 + mi * 16 + gl, r1 = r0 + 8;
#pragma unroll
        for (int ni = 0; ni < NI; ni++) {
            int cb = wcol * 32 + ni * 8 + 2 * tig;
            float2 x0 = __half22float2(*reinterpret_cast<const __half2*>(xg_t + (size_t)r0 * Gg + bn + cb));
            float2 x1 = __half22float2(*reinterpret_cast<const __half2*>(xg_t + (size_t)r1 * Gg + bn + cb));
            sC[r0 * SCLD + cb]     = acc[mi][ni][0] + x0.x;
            sC[r0 * SCLD + cb + 1] = acc[mi][ni][1] + x0.y;
            sC[r1 * SCLD + cb]     = acc[mi][ni][2] + x1.x;
            sC[r1 * SCLD + cb + 1] = acc[mi][ni][3] + x1.y;
        }
    }
    __syncthreads();

    // LSTM elementwise: 1024 (batch, quad) pairs, 8 per thread
#pragma unroll
    for (int it = 0; it < 8; it++) {
        int pair = it * 128 + tid;
        int b = pair >> 4, qq = pair & 15;
        int jg = (bn >> 2) + qq;   // hidden unit index
        float gi = sC[b * SCLD + 4 * qq + 0];
        float gf = sC[b * SCLD + 4 * qq + 1];
        float gg = sC[b * SCLD + 4 * qq + 2];
        float go = sC[b * SCLD + 4 * qq + 3];
        float cp = first ? 0.0f : c_prev[b * Hh + jg];
        float si = 1.0f / (1.0f + expf(-gi));
        float sf = 1.0f / (1.0f + expf(-gf));
        float so = 1.0f / (1.0f + expf(-go));
        float cn = sf * cp + si * tanhf(gg);
        float hn = so * tanhf(cn);
        c_out[b * Hh + jg] = cn;
        h_out[b * Hh + jg] = hn;
        h16_o[b * Hh + jg] = __float2half(hn);
    }
}

// ---------- batched projections + gumbel softmax (one CTA per (t,b)) ----------
__global__ void __launch_bounds__(256, 1)
proj_kernel(const float* __restrict__ hhist, const float* __restrict__ chist,
            const float* __restrict__ Wpred, const float* __restrict__ bpred,
            const float* __restrict__ Wpredc, const float* __restrict__ bpredc,
            const float* __restrict__ Wutil, const float* __restrict__ butil,
            const float* __restrict__ Wuse, const float* __restrict__ buse,
            const float* __restrict__ gum, float* __restrict__ out) {
    const int tb = blockIdx.x;          // t*64+b
    const int t = tb >> 6;
    const int tid = threadIdx.x;
    const float* hr = hhist + (size_t)tb * Hh;
    const float* cr = chist + (size_t)tb * Hh;
    float v[7] = {0, 0, 0, 0, 0, 0, 0};

    for (int j = tid; j < Hh; j += 256) {
        float hn = hr[j], cn = cr[j];
        v[0] += hn * Wpred[j];       v[1] += hn * Wpred[Hh + j];
        v[2] += cn * Wpredc[j];      v[3] += cn * Wpredc[Hh + j];
        v[4] += hn * Wutil[j];
        v[5] += hn * Wuse[j];        v[6] += hn * Wuse[Hh + j];
    }
#pragma unroll
    for (int o = 16; o > 0; o >>= 1)
#pragma unroll
        for (int q = 0; q < 7; q++) v[q] += __shfl_xor_sync(0xffffffffu, v[q], o);

    __shared__ float red[8][7];
    int wid = tid >> 5, lane = tid & 31;
    if (lane == 0)
#pragma unroll
        for (int q = 0; q < 7; q++) red[wid][q] = v[q];
    __syncthreads();

    if (tid == 0) {
        float s[7];
#pragma unroll
        for (int q = 0; q < 7; q++) {
            float a = 0;
#pragma unroll
            for (int w = 0; w < 8; w++) a += red[w][q];
            s[q] = a;
        }
        out[OUT_H + tb * 2 + 0] = s[0] + bpred[0];
        out[OUT_H + tb * 2 + 1] = s[1] + bpred[1];
        out[OUT_C + tb * 2 + 0] = s[2] + bpredc[0];
        out[OUT_C + tb * 2 + 1] = s[3] + bpredc[1];
        out[OUT_U + tb] = s[4] + butil[0];
        float z0 = s[5] + buse[0] + gum[tb * 2 + 0];
        float z1 = s[6] + buse[1] + gum[tb * 2 + 1];
        float mz = fmaxf(z0, z1);
        float e0 = expf(z0 - mz), e1 = expf(z1 - mz);
        float inv = 1.0f / (e0 + e1);
        if (t >= 1) {
            int b = tb & 63;
            out[OUT_W + ((t - 1) * Bb + b) * 2 + 0] = e0 * inv;
            out[OUT_W + ((t - 1) * Bb + b) * 2 + 1] = e1 * inv;
        }
    }
}

// ---------- launch ----------
extern "C" void kernel_launch(void* const* d_in, const int* in_sizes, int n_in,
                              void* d_out, int out_size) {
    const float* feature = (const float*)d_in[0];
    const float* W_ih    = (const float*)d_in[1];
    const float* W_hh    = (const float*)d_in[2];
    const float* b_ih    = (const float*)d_in[3];
    const float* b_hh    = (const float*)d_in[4];
    const float* W_pred  = (const float*)d_in[5];
    const float* b_pred  = (const float*)d_in[6];
    const float* W_predc = (const float*)d_in[7];
    const float* b_predc = (const float*)d_in[8];
    const float* W_util  = (const float*)d_in[9];
    const float* b_util  = (const float*)d_in[10];
    const float* W_use   = (const float*)d_in[11];
    const float* b_use   = (const float*)d_in[12];
    float* out = (float*)d_out;

    void *p_f, *p_wih, *p_whh, *p_xg, *p_ch, *p_hh, *p_h16, *p_gum, *p_bias;
    cudaGetSymbolAddress(&p_f, g_featT);
    cudaGetSymbolAddress(&p_wih, g_wih);   cudaGetSymbolAddress(&p_whh, g_whh);
    cudaGetSymbolAddress(&p_xg, g_xg);
    cudaGetSymbolAddress(&p_ch, g_chist);  cudaGetSymbolAddress(&p_hh, g_hhist);
    cudaGetSymbolAddress(&p_h16, g_h16);
    cudaGetSymbolAddress(&p_gum, g_gumbel); cudaGetSymbolAddress(&p_bias, g_bias);

    constexpr int SMEM_BIG = 3 * (128 * 72 + 128 * 72) * 2;   // 110592
    cudaFuncSetAttribute((const void*)gemm_pipe_kernel<128,128,64,3,2,4,64,32>,
                         cudaFuncAttributeMaxDynamicSharedMemorySize, SMEM_BIG);
    cudaFuncSetAttribute((const void*)step_fused_kernel,
                         cudaFuncAttributeMaxDynamicSharedMemorySize, SMEM_STEP);

    int prLow = 0, prHigh = 0;
    cudaDeviceGetStreamPriorityRange(&prLow, &prHigh);
    cudaStream_t s2;
    cudaStreamCreateWithPriority(&s2, cudaStreamNonBlocking, prLow);   // lowest priority
    cudaEvent_t evFork, evChunk[6];
    cudaEventCreateWithFlags(&evFork, cudaEventDisableTiming);
    for (int c = 0; c < 6; c++) cudaEventCreateWithFlags(&evChunk[c], cudaEventDisableTiming);

    // prep on default stream
    gumbel_kernel<<<48, 256>>>((float*)p_gum);
    bias_perm_kernel<<<(Gg + 255) / 256, 256>>>(b_ih, b_hh, (float*)p_bias);
    perm_h16_kernel<<<(Gg * Ff / 4 + 255) / 256, 256>>>(W_ih, (__half*)p_wih, Ff);
    perm_h16_kernel<<<(Gg * Hh / 4 + 255) / 256, 256>>>(W_hh, (__half*)p_whh, Hh);
    feat_prep_kernel<<<(M1 * Ff / 4 + 255) / 256, 256>>>(feature, (__half*)p_f);

    // fork s2 and run the input GEMM as 6 M-chunks (16 timesteps each)
    cudaEventRecord(evFork, 0);
    cudaStreamWaitEvent(s2, evFork, 0);
    constexpr int CHUNK_ROWS = 1024;   // 16 t * 64 b
    for (int c = 0; c < 6; c++) {
        gemm_pipe_kernel<128,128,64,3,2,4,64,32>
            <<<dim3(Gg / 128, CHUNK_ROWS / 128), 256, SMEM_BIG, s2>>>(
            (const __half*)p_f + (size_t)c * CHUNK_ROWS * Ff,
            (const __half*)p_wih, (const float*)p_bias,
            (__half*)p_xg + (size_t)c * CHUNK_ROWS * Gg, Gg, Ff);
        cudaEventRecord(evChunk[c], s2);
    }

    // recurrence on default stream; step 16c gated on chunk c
    for (int t = 0; t < Tt; t++) {
        if ((t & 15) == 0) cudaStreamWaitEvent(0, evChunk[t >> 4], 0);
        step_fused_kernel<<<Gg / 64, 128, SMEM_STEP>>>(
            (const __half*)p_h16 + (size_t)((t + 1) & 1) * (Bb * Hh),   // read h(t-1)
            (const __half*)p_whh,
            (const __half*)p_xg + (size_t)t * Bb * Gg,
            (const float*)p_ch + (size_t)(t - 1) * Bb * Hh,
            (float*)p_ch + (size_t)t * Bb * Hh,
            (float*)p_hh + (size_t)t * Bb * Hh,
            (__half*)p_h16 + (size_t)(t & 1) * (Bb * Hh),               // write h(t)
            t == 0 ? 1 : 0);
    }

    proj_kernel<<<M1, 256>>>((const float*)p_hh, (const float*)p_ch,
                             W_pred, b_pred, W_predc, b_predc,
                             W_util, b_util, W_use, b_use,
                             (const float*)p_gum, out);

    for (int c = 0; c < 6; c++) cudaEventDestroy(evChunk[c]);
    cudaEventDestroy(evFork);
    cudaStreamDestroy(s2);
}

// round 14
// speedup vs baseline: 1.0563x; 1.0563x over previous
#include <cuda_runtime.h>
#include <cuda_fp16.h>
#include <cstdint>

#define DEV_INLINE __device__ __forceinline__

constexpr int Bb = 64, Tt = 96, Ff = 2048, Hh = 2048, Gg = 4 * Hh;
constexpr int M1 = Tt * Bb;                 // 6144

constexpr int OUT_H = 0;
constexpr int OUT_C = OUT_H + Tt * Bb * 2;
constexpr int OUT_U = OUT_C + Tt * Bb * 2;
constexpr int OUT_W = OUT_U + Tt * Bb;

__device__ __half g_featT[M1 * Ff];
__device__ __half g_wih[Gg * Ff];        // permuted rows
__device__ __half g_whh[Gg * Hh];        // permuted rows
__device__ __half g_xg[(size_t)M1 * Gg]; // permuted cols, fp16
__device__ float  g_chist[(size_t)M1 * Hh];
__device__ float  g_hhist[(size_t)M1 * Hh];
__device__ __half g_h16[2][Bb * Hh];     // double buffer (parity by t)
__device__ float  g_gumbel[Tt * Bb * 2];
__device__ float  g_bias[Gg];            // permuted

// ---------- threefry2x32 gumbel, key=(0,42), partitionable counter scheme ----------
DEV_INLINE uint32_t rotl32(uint32_t x, int d) { return (x << d) | (x >> (32 - d)); }
DEV_INLINE void tfr(uint32_t& x0, uint32_t& x1, int r) { x0 += x1; x1 = rotl32(x1, r); x1 ^= x0; }

DEV_INLINE float bits_to_gumbel(uint32_t bits) {
    float u0 = __uint_as_float((bits >> 9) | 0x3f800000u) - 1.0f;
    const float tiny = 1.1754943508222875e-38f;
    float u = fmaxf(u0 * (1.0f - tiny) + tiny, tiny);
    return -logf(-logf(u));
}

__global__ void gumbel_kernel(float* __restrict__ out) {
    int i = blockIdx.x * blockDim.x + threadIdx.x;
    if (i >= Tt * Bb * 2) return;
    uint32_t x0 = 0u, x1 = (uint32_t)i;
    const uint32_t k0 = 0u, k1 = 42u, k2 = 0u ^ 42u ^ 0x1BD11BDAu;
    x0 += k0; x1 += k1;
    tfr(x0,x1,13); tfr(x0,x1,15); tfr(x0,x1,26); tfr(x0,x1,6);
    x0 += k1; x1 += k2 + 1u;
    tfr(x0,x1,17); tfr(x0,x1,29); tfr(x0,x1,16); tfr(x0,x1,24);
    x0 += k2; x1 += k0 + 2u;
    tfr(x0,x1,13); tfr(x0,x1,15); tfr(x0,x1,26); tfr(x0,x1,6);
    x0 += k0; x1 += k1 + 3u;
    tfr(x0,x1,17); tfr(x0,x1,29); tfr(x0,x1,16); tfr(x0,x1,24);
    x0 += k1; x1 += k2 + 4u;
    tfr(x0,x1,13); tfr(x0,x1,15); tfr(x0,x1,26); tfr(x0,x1,6);
    x0 += k2; x1 += k0 + 5u;
    out[i] = bits_to_gumbel(x0 ^ x1);
}

// ---------- fp32 -> fp16 prep ----------
DEV_INLINE void h4store(float4 v, __half* o) {
    __half2* o2 = reinterpret_cast<__half2*>(o);
    o2[0] = __floats2half2_rn(v.x, v.y);
    o2[1] = __floats2half2_rn(v.z, v.w);
}

__global__ void perm_h16_kernel(const float* __restrict__ in, __half* __restrict__ o, int K) {
    int i = blockIdx.x * blockDim.x + threadIdx.x;
    if (i >= Gg * K / 4) return;
    int e = i * 4;
    int r = e / K, k = e % K;
    int orig = ((r & 3) << 11) + (r >> 2);
    float4 v = *reinterpret_cast<const float4*>(in + (size_t)orig * K + k);
    h4store(v, o + (size_t)e);
}

__global__ void feat_prep_kernel(const float* __restrict__ feat, __half* __restrict__ o) {
    int i = blockIdx.x * blockDim.x + threadIdx.x;
    if (i >= (M1 * Ff) / 4) return;
    int e = i * 4, m = e >> 11, f = e & 2047, b = m & 63, t = m >> 6;
    float4 v = *reinterpret_cast<const float4*>(feat + ((size_t)b * Tt + t) * Ff + f);
    h4store(v, o + (size_t)e);
}

__global__ void bias_perm_kernel(const float* __restrict__ a, const float* __restrict__ b,
                                 float* __restrict__ o) {
    int r = blockIdx.x * blockDim.x + threadIdx.x;
    if (r >= Gg) return;
    int orig = ((r & 3) << 11) + (r >> 2);
    o[r] = a[orig] + b[orig];
}

// ---------- mma + cp.async helpers ----------
DEV_INLINE void mma16816h(float c[4], const uint32_t a[4], const uint32_t b[2]) {
    asm volatile(
        "mma.sync.aligned.m16n8k16.row.col.f32.f16.f16.f32 "
        "{%0,%1,%2,%3}, {%4,%5,%6,%7}, {%8,%9}, {%0,%1,%2,%3};\n"
        : "+f"(c[0]), "+f"(c[1]), "+f"(c[2]), "+f"(c[3])
        : "r"(a[0]), "r"(a[1]), "r"(a[2]), "r"(a[3]), "r"(b[0]), "r"(b[1]));
}

DEV_INLINE void cp_async16(__half* smem_ptr, const __half* gptr) {
    uint32_t s = (uint32_t)__cvta_generic_to_shared(smem_ptr);
    asm volatile("cp.async.cg.shared.global [%0], [%1], 16;\n" :: "r"(s), "l"(gptr));
}
DEV_INLINE void cp_commit() { asm volatile("cp.async.commit_group;\n" ::: "memory"); }
template <int N> DEV_INLINE void cp_wait() { asm volatile("cp.async.wait_group %0;\n" :: "n"(N) : "memory"); }

// ---------- pipelined fp16 GEMM (big input GEMM), fp16 out + fp32 bias ----------
template <int BM, int BN, int BK, int STAGES, int WROWS, int WCOLS, int WM, int WN>
__global__ void __launch_bounds__(WROWS * WCOLS * 32, 1)
gemm_pipe_kernel(const __half* __restrict__ A, const __half* __restrict__ B,
                 const float* __restrict__ addVec,
                 __half* __restrict__ Cout, int N, int K) {
    constexpr int NT = WROWS * WCOLS * 32;
    constexpr int LD = BK + 8, LD32 = LD / 2;
    constexpr int MI = WM / 16, NI = WN / 8;
    constexpr int A_ELE = BM * LD, B_ELE = BN * LD;
    constexpr int STAGE_ELE = A_ELE + B_ELE;

    extern __shared__ __half smem_g[];

    const int tid = threadIdx.x, wid = tid >> 5, lane = tid & 31;
    const int wrow = wid / WCOLS, wcol = wid % WCOLS;
    const int gl = lane >> 2, tig = lane & 3;
    const int bm = blockIdx.y * BM, bn = blockIdx.x * BN;
    const int KT = K / BK;

    float acc[MI][NI][4];
#pragma unroll
    for (int mi = 0; mi < MI; mi++)
#pragma unroll
        for (int ni = 0; ni < NI; ni++)
#pragma unroll
            for (int q = 0; q < 4; q++) acc[mi][ni][q] = 0.0f;

    auto load_stage = [&](int stg, int kt) {
        __half* sA = smem_g + stg * STAGE_ELE;
        __half* sB = sA + A_ELE;
        int k0 = kt * BK;
        for (int c = tid; c < BM * BK / 8; c += NT) {
            int r = c / (BK / 8), cc = (c % (BK / 8)) * 8;
            cp_async16(&sA[r * LD + cc], A + (size_t)(bm + r) * K + k0 + cc);
        }
        for (int c = tid; c < BN * BK / 8; c += NT) {
            int r = c / (BK / 8), cc = (c % (BK / 8)) * 8;
            cp_async16(&sB[r * LD + cc], B + (size_t)(bn + r) * K + k0 + cc);
        }
    };

#pragma unroll
    for (int s = 0; s < STAGES - 1; s++) {
        if (s < KT) load_stage(s, s);
        cp_commit();
    }

    for (int kt = 0; kt < KT; kt++) {
        cp_wait<STAGES - 2>();
        __syncthreads();
        int nk = kt + STAGES - 1;
        if (nk < KT) load_stage(nk % STAGES, nk);
        cp_commit();

        int stg = kt % STAGES;
        const uint32_t* A32 = reinterpret_cast<const uint32_t*>(smem_g + stg * STAGE_ELE);
        const uint32_t* B32 = A32 + A_ELE / 2;

#pragma unroll
        for (int ks = 0; ks < BK / 16; ks++) {
            uint32_t ah[MI][4];
#pragma unroll
            for (int mi = 0; mi < MI; mi++) {
                int r = wrow * WM + mi * 16 + gl;
                int p0 = r * LD32 + ks * 8 + tig, p1 = (r + 8) * LD32 + ks * 8 + tig;
                ah[mi][0] = A32[p0]; ah[mi][1] = A32[p1];
                ah[mi][2] = A32[p0 + 4]; ah[mi][3] = A32[p1 + 4];
            }
#pragma unroll
            for (int ni = 0; ni < NI; ni++) {
                int r = wcol * WN + ni * 8 + gl;
                int p = r * LD32 + ks * 8 + tig;
                uint32_t bh[2] = {B32[p], B32[p + 4]};
#pragma unroll
                for (int mi = 0; mi < MI; mi++) mma16816h(acc[mi][ni], ah[mi], bh);
            }
        }
    }

#pragma unroll
    for (int mi = 0; mi < MI; mi++) {
        int r0 = bm + wrow * WM + mi * 16 + gl, r1 = r0 + 8;
#pragma unroll
        for (int ni = 0; ni < NI; ni++) {
            int cb = bn + wcol * WN + ni * 8 + 2 * tig;
            float2 av = *reinterpret_cast<const float2*>(addVec + cb);
            __half2 h0 = __floats2half2_rn(acc[mi][ni][0] + av.x, acc[mi][ni][1] + av.y);
            __half2 h1 = __floats2half2_rn(acc[mi][ni][2] + av.x, acc[mi][ni][3] + av.y);
            *reinterpret_cast<__half2*>(Cout + (size_t)r0 * N + cb) = h0;
            *reinterpret_cast<__half2*>(Cout + (size_t)r1 * N + cb) = h1;
        }
    }
}

// ---------- fused step: gates GEMM (fp16) + LSTM; SBK=128, 3 stages, 16 kt iters ----------
constexpr int SBK = 128, SSTG = 3;
constexpr int SLD = SBK + 8, SLD32 = SLD / 2;          // 136 / 68
constexpr int S_AELE = 64 * SLD;                       // 8704 halves
constexpr int S_STAGE = 2 * S_AELE;                    // 17408 halves
constexpr int SMEM_STEP = SSTG * S_STAGE * 2;          // 104448 B
constexpr int SCLD = 68;                               // staging ld (floats)

__global__ void __launch_bounds__(128, 1)
step_fused_kernel(const __half* __restrict__ Hc, const __half* __restrict__ Wp,
                  const __half* __restrict__ xg_t,     // [64][Gg] permuted cols, fp16
                  const float* __restrict__ c_prev,
                  float* __restrict__ c_out, float* __restrict__ h_out,
                  __half* __restrict__ h16_o, int first) {
    constexpr int MI = 2, NI = 4;
    extern __shared__ __half smem_s[];

    const int tid = threadIdx.x, wid = tid >> 5, lane = tid & 31;
    const int wrow = wid >> 1, wcol = wid & 1;
    const int gl = lane >> 2, tig = lane & 3;
    const int bn = blockIdx.x * 64;
    constexpr int KT = Hh / SBK;   // 16

    float acc[MI][NI][4];
#pragma unroll
    for (int mi = 0; mi < MI; mi++)
#pragma unroll
        for (int ni = 0; ni < NI; ni++)
#pragma unroll
            for (int q = 0; q < 4; q++) acc[mi][ni][q] = 0.0f;

    if (!first) {
        auto load_stage = [&](int stg, int kt) {
            __half* sA = smem_s + stg * S_STAGE;
            __half* sB = sA + S_AELE;
            int k0 = kt * SBK;
            for (int c = tid; c < 64 * SBK / 8; c += 128) {
                int r = c >> 4, cc = (c & 15) * 8;
                cp_async16(&sA[r * SLD + cc], Hc + (size_t)r * Hh + k0 + cc);
                cp_async16(&sB[r * SLD + cc], Wp + (size_t)(bn + r) * Hh + k0 + cc);
            }
        };

#pragma unroll
        for (int s = 0; s < SSTG - 1; s++) { load_stage(s, s); cp_commit(); }

        for (int kt = 0; kt < KT; kt++) {
            cp_wait<SSTG - 2>();
            __syncthreads();
            int nk = kt + SSTG - 1;
            if (nk < KT) load_stage(nk % SSTG, nk);
            cp_commit();

            int stg = kt % SSTG;
            const uint32_t* A32 = reinterpret_cast<const uint32_t*>(smem_s + stg * S_STAGE);
            const uint32_t* B32 = A32 + S_AELE / 2;

#pragma unroll
            for (int ks = 0; ks < SBK / 16; ks++) {
                uint32_t ah[MI][4];
#pragma unroll
                for (int mi = 0; mi < MI; mi++) {
                    int r = wrow * 32 + mi * 16 + gl;
                    int p0 = r * SLD32 + ks * 8 + tig, p1 = (r + 8) * SLD32 + ks * 8 + tig;
                    ah[mi][0] = A32[p0]; ah[mi][1] = A32[p1];
                    ah[mi][2] = A32[p0 + 4]; ah[mi][3] = A32[p1 + 4];
                }
#pragma unroll
                for (int ni = 0; ni < NI; ni++) {
                    int r = wcol * 32 + ni * 8 + gl;
                    int p = r * SLD32 + ks * 8 + tig;
                    uint32_t bh[2] = {B32[p], B32[p + 4]};
#pragma unroll
                    for (int mi = 0; mi < MI; mi++) mma16816h(acc[mi][ni], ah[mi], bh);
                }
            }
        }
        cp_wait<0>();
    }
    __syncthreads();

    // stage gates = acc + xg (fp16) into smem
    float* sC = reinterpret_cast<float*>(smem_s);   // [64][SCLD]
#pragma unroll
    for (int mi = 0; mi < MI; mi++) {
        int r0 = wrow * 32 + mi * 16 + gl, r1 = r0 + 8;
#pragma unroll
        for (int ni = 0; ni < NI; ni++) {
            int cb = wcol * 32 + ni * 8 + 2 * tig;
            float2 x0 = __half22float2(*reinterpret_cast<const __half2*>(xg_t + (size_t)r0 * Gg + bn + cb));
            float2 x1 = __half22float2(*reinterpret_cast<const __half2*>(xg_t + (size_t)r1 * Gg + bn + cb));
            sC[r0 * SCLD + cb]     = acc[mi][ni][0] + x0.x;
            sC[r0 * SCLD + cb + 1] = acc[mi][ni][1] + x0.y;
            sC[r1 * SCLD + cb]     = acc[mi][ni][2] + x1.x;
            sC[r1 * SCLD + cb + 1] = acc[mi][ni][3] + x1.y;
        }
    }
    __syncthreads();

    // LSTM elementwise: 1024 (batch, quad) pairs, 8 per thread
#pragma unroll
    for (int it = 0; it < 8; it++) {
        int pair = it * 128 + tid;
        int b = pair >> 4, qq = pair & 15;
        int jg = (bn >> 2) + qq;   // hidden unit index
        float gi = sC[b * SCLD + 4 * qq + 0];
        float gf = sC[b * SCLD + 4 * qq + 1];
        float gg = sC[b * SCLD + 4 * qq + 2];
        float go = sC[b * SCLD + 4 * qq + 3];
        float cp = first ? 0.0f : c_prev[b * Hh + jg];
        float si = 1.0f / (1.0f + expf(-gi));
        float sf = 1.0f / (1.0f + expf(-gf));
        float so = 1.0f / (1.0f + expf(-go));
        float cn = sf * cp + si * tanhf(gg);
        float hn = so * tanhf(cn);
        c_out[b * Hh + jg] = cn;
        h_out[b * Hh + jg] = hn;
        h16_o[b * Hh + jg] = __float2half(hn);
    }
}

// ---------- batched projections + gumbel softmax (one CTA per (t,b)) ----------
__global__ void __launch_bounds__(256, 1)
proj_kernel(const float* __restrict__ hhist, const float* __restrict__ chist,
            const float* __restrict__ Wpred, const float* __restrict__ bpred,
            const float* __restrict__ Wpredc, const float* __restrict__ bpredc,
            const float* __restrict__ Wutil, const float* __restrict__ butil,
            const float* __restrict__ Wuse, const float* __restrict__ buse,
            const float* __restrict__ gum, float* __restrict__ out) {
    const int tb = blockIdx.x;          // t*64+b
    const int t = tb >> 6;
    const int tid = threadIdx.x;
    const float* hr = hhist + (size_t)tb * Hh;
    const float* cr = chist + (size_t)tb * Hh;
    float v[7] = {0, 0, 0, 0, 0, 0, 0};

    for (int j = tid; j < Hh; j += 256) {
        float hn = hr[j], cn = cr[j];
        v[0] += hn * Wpred[j];       v[1] += hn * Wpred[Hh + j];
        v[2] += cn * Wpredc[j];      v[3] += cn * Wpredc[Hh + j];
        v[4] += hn * Wutil[j];
        v[5] += hn * Wuse[j];        v[6] += hn * Wuse[Hh + j];
    }
#pragma unroll
    for (int o = 16; o > 0; o >>= 1)
#pragma unroll
        for (int q = 0; q < 7; q++) v[q] += __shfl_xor_sync(0xffffffffu, v[q], o);

    __shared__ float red[8][7];
    int wid = tid >> 5, lane = tid & 31;
    if (lane == 0)
#pragma unroll
        for (int q = 0; q < 7; q++) red[wid][q] = v[q];
    __syncthreads();

    if (tid == 0) {
        float s[7];
#pragma unroll
        for (int q = 0; q < 7; q++) {
            float a = 0;
#pragma unroll
            for (int w = 0; w < 8; w++) a += red[w][q];
            s[q] = a;
        }
        out[OUT_H + tb * 2 + 0] = s[0] + bpred[0];
        out[OUT_H + tb * 2 + 1] = s[1] + bpred[1];
        out[OUT_C + tb * 2 + 0] = s[2] + bpredc[0];
        out[OUT_C + tb * 2 + 1] = s[3] + bpredc[1];
        out[OUT_U + tb] = s[4] + butil[0];
        float z0 = s[5] + buse[0] + gum[tb * 2 + 0];
        float z1 = s[6] + buse[1] + gum[tb * 2 + 1];
        float mz = fmaxf(z0, z1);
        float e0 = expf(z0 - mz), e1 = expf(z1 - mz);
        float inv = 1.0f / (e0 + e1);
        if (t >= 1) {
            int b = tb & 63;
            out[OUT_W + ((t - 1) * Bb + b) * 2 + 0] = e0 * inv;
            out[OUT_W + ((t - 1) * Bb + b) * 2 + 1] = e1 * inv;
        }
    }
}

// ---------- launch ----------
extern "C" void kernel_launch(void* const* d_in, const int* in_sizes, int n_in,
                              void* d_out, int out_size) {
    const float* feature = (const float*)d_in[0];
    const float* W_ih    = (const float*)d_in[1];
    const float* W_hh    = (const float*)d_in[2];
    const float* b_ih    = (const float*)d_in[3];
    const float* b_hh    = (const float*)d_in[4];
    const float* W_pred  = (const float*)d_in[5];
    const float* b_pred  = (const float*)d_in[6];
    const float* W_predc = (const float*)d_in[7];
    const float* b_predc = (const float*)d_in[8];
    const float* W_util  = (const float*)d_in[9];
    const float* b_util  = (const float*)d_in[10];
    const float* W_use   = (const float*)d_in[11];
    const float* b_use   = (const float*)d_in[12];
    float* out = (float*)d_out;

    void *p_f, *p_wih, *p_whh, *p_xg, *p_ch, *p_hh, *p_h16, *p_gum, *p_bias;
    cudaGetSymbolAddress(&p_f, g_featT);
    cudaGetSymbolAddress(&p_wih, g_wih);   cudaGetSymbolAddress(&p_whh, g_whh);
    cudaGetSymbolAddress(&p_xg, g_xg);
    cudaGetSymbolAddress(&p_ch, g_chist);  cudaGetSymbolAddress(&p_hh, g_hhist);
    cudaGetSymbolAddress(&p_h16, g_h16);
    cudaGetSymbolAddress(&p_gum, g_gumbel); cudaGetSymbolAddress(&p_bias, g_bias);

    constexpr int SMEM_BIG = 4 * (128 * 72 + 128 * 72) * 2;   // 147456
    cudaFuncSetAttribute((const void*)gemm_pipe_kernel<128,128,64,4,2,4,64,32>,
                         cudaFuncAttributeMaxDynamicSharedMemorySize, SMEM_BIG);
    cudaFuncSetAttribute((const void*)step_fused_kernel,
                         cudaFuncAttributeMaxDynamicSharedMemorySize, SMEM_STEP);

    gumbel_kernel<<<48, 256>>>((float*)p_gum);
    bias_perm_kernel<<<(Gg + 255) / 256, 256>>>(b_ih, b_hh, (float*)p_bias);
    perm_h16_kernel<<<(Gg * Ff / 4 + 255) / 256, 256>>>(W_ih, (__half*)p_wih, Ff);
    perm_h16_kernel<<<(Gg * Hh / 4 + 255) / 256, 256>>>(W_hh, (__half*)p_whh, Hh);
    feat_prep_kernel<<<(M1 * Ff / 4 + 255) / 256, 256>>>(feature, (__half*)p_f);

    // xg = featT @ Wih_perm^T + bias_perm (permuted gate columns, fp16), serial
    gemm_pipe_kernel<128,128,64,4,2,4,64,32><<<dim3(Gg / 128, M1 / 128), 256, SMEM_BIG>>>(
        (const __half*)p_f, (const __half*)p_wih,
        (const float*)p_bias, (__half*)p_xg, Gg, Ff);

    for (int t = 0; t < Tt; t++) {
        step_fused_kernel<<<Gg / 64, 128, SMEM_STEP>>>(
            (const __half*)p_h16 + (size_t)((t + 1) & 1) * (Bb * Hh),   // read h(t-1)
            (const __half*)p_whh,
            (const __half*)p_xg + (size_t)t * Bb * Gg,
            (const float*)p_ch + (size_t)(t - 1) * Bb * Hh,
            (float*)p_ch + (size_t)t * Bb * Hh,
            (float*)p_hh + (size_t)t * Bb * Hh,
            (__half*)p_h16 + (size_t)(t & 1) * (Bb * Hh),               // write h(t)
            t == 0 ? 1 : 0);
    }

    proj_kernel<<<M1, 256>>>((const float*)p_hh, (const float*)p_ch,
                             W_pred, b_pred, W_predc, b_predc,
                             W_util, b_util, W_use, b_use,
                             (const float*)p_gum, out);
}

// round 15
// speedup vs baseline: 1.1682x; 1.1059x over previous
#include <cuda_runtime.h>
#include <cuda_fp16.h>
#include <cstdint>

#define DEV_INLINE __device__ __forceinline__

constexpr int Bb = 64, Tt = 96, Ff = 2048, Hh = 2048, Gg = 4 * Hh;
constexpr int M1 = Tt * Bb;                 // 6144

constexpr int OUT_H = 0;
constexpr int OUT_C = OUT_H + Tt * Bb * 2;
constexpr int OUT_U = OUT_C + Tt * Bb * 2;
constexpr int OUT_W = OUT_U + Tt * Bb;

__device__ __half g_featT[M1 * Ff];
__device__ __half g_wih[Gg * Ff];            // permuted rows (big GEMM)
__device__ __half g_whh_blk[Gg * Hh];        // blocked+swizzled [tile128][kt16][64][128]
__device__ __half g_xg[(size_t)M1 * Gg];     // permuted cols, fp16
__device__ float  g_chist[(size_t)M1 * Hh];
__device__ float  g_hhist[(size_t)M1 * Hh];
__device__ __half g_h16blk[2][16 * 64 * 128];// blocked+swizzled h, double buffer
__device__ float  g_gumbel[Tt * Bb * 2];
__device__ float  g_bias[Gg];                // permuted

// ---------- threefry2x32 gumbel, key=(0,42), partitionable counter scheme ----------
DEV_INLINE uint32_t rotl32(uint32_t x, int d) { return (x << d) | (x >> (32 - d)); }
DEV_INLINE void tfr(uint32_t& x0, uint32_t& x1, int r) { x0 += x1; x1 = rotl32(x1, r); x1 ^= x0; }

DEV_INLINE float bits_to_gumbel(uint32_t bits) {
    float u0 = __uint_as_float((bits >> 9) | 0x3f800000u) - 1.0f;
    const float tiny = 1.1754943508222875e-38f;
    float u = fmaxf(u0 * (1.0f - tiny) + tiny, tiny);
    return -logf(-logf(u));
}

__global__ void gumbel_kernel(float* __restrict__ out) {
    int i = blockIdx.x * blockDim.x + threadIdx.x;
    if (i >= Tt * Bb * 2) return;
    uint32_t x0 = 0u, x1 = (uint32_t)i;
    const uint32_t k0 = 0u, k1 = 42u, k2 = 0u ^ 42u ^ 0x1BD11BDAu;
    x0 += k0; x1 += k1;
    tfr(x0,x1,13); tfr(x0,x1,15); tfr(x0,x1,26); tfr(x0,x1,6);
    x0 += k1; x1 += k2 + 1u;
    tfr(x0,x1,17); tfr(x0,x1,29); tfr(x0,x1,16); tfr(x0,x1,24);
    x0 += k2; x1 += k0 + 2u;
    tfr(x0,x1,13); tfr(x0,x1,15); tfr(x0,x1,26); tfr(x0,x1,6);
    x0 += k0; x1 += k1 + 3u;
    tfr(x0,x1,17); tfr(x0,x1,29); tfr(x0,x1,16); tfr(x0,x1,24);
    x0 += k1; x1 += k2 + 4u;
    tfr(x0,x1,13); tfr(x0,x1,15); tfr(x0,x1,26); tfr(x0,x1,6);
    x0 += k2; x1 += k0 + 5u;
    out[i] = bits_to_gumbel(x0 ^ x1);
}

// ---------- fp32 -> fp16 prep ----------
DEV_INLINE void h4store(float4 v, __half* o) {
    __half2* o2 = reinterpret_cast<__half2*>(o);
    o2[0] = __floats2half2_rn(v.x, v.y);
    o2[1] = __floats2half2_rn(v.z, v.w);
}

// W_ih: row-permuted, row-major (for the big GEMM)
__global__ void perm_h16_kernel(const float* __restrict__ in, __half* __restrict__ o, int K) {
    int i = blockIdx.x * blockDim.x + threadIdx.x;
    if (i >= Gg * K / 4) return;
    int e = i * 4;
    int r = e / K, k = e % K;
    int orig = ((r & 3) << 11) + (r >> 2);
    float4 v = *reinterpret_cast<const float4*>(in + (size_t)orig * K + k);
    h4store(v, o + (size_t)e);
}

// W_hh: permuted rows -> blocked [tile][kt][r][128] with 16B-chunk swizzle
__global__ void perm_whh_blk_kernel(const float* __restrict__ in, __half* __restrict__ o) {
    int i = blockIdx.x * blockDim.x + threadIdx.x;
    if (i >= 128 * 16 * 64 * 16) return;     // one 16B chunk (8 halves) per thread
    int chunk = i & 15;
    int r     = (i >> 4) & 63;
    int kt    = (i >> 10) & 15;
    int tile  = i >> 14;
    int pr = tile * 64 + r;
    int orig = ((pr & 3) << 11) + (pr >> 2);
    int k0 = kt * 128 + chunk * 8;
    const float* src = in + (size_t)orig * Hh + k0;
    float4 a = *reinterpret_cast<const float4*>(src);
    float4 b = *reinterpret_cast<const float4*>(src + 4);
    __half hh[8];
    hh[0]=__float2half(a.x); hh[1]=__float2half(a.y); hh[2]=__float2half(a.z); hh[3]=__float2half(a.w);
    hh[4]=__float2half(b.x); hh[5]=__float2half(b.y); hh[6]=__float2half(b.z); hh[7]=__float2half(b.w);
    size_t dst = ((size_t)(tile * 16 + kt) * 64 + r) * 128 + ((chunk ^ (r & 7)) << 3);
    *reinterpret_cast<uint4*>(o + dst) = *reinterpret_cast<uint4*>(hh);
}

__global__ void feat_prep_kernel(const float* __restrict__ feat, __half* __restrict__ o) {
    int i = blockIdx.x * blockDim.x + threadIdx.x;
    if (i >= (M1 * Ff) / 4) return;
    int e = i * 4, m = e >> 11, f = e & 2047, b = m & 63, t = m >> 6;
    float4 v = *reinterpret_cast<const float4*>(feat + ((size_t)b * Tt + t) * Ff + f);
    h4store(v, o + (size_t)e);
}

__global__ void bias_perm_kernel(const float* __restrict__ a, const float* __restrict__ b,
                                 float* __restrict__ o) {
    int r = blockIdx.x * blockDim.x + threadIdx.x;
    if (r >= Gg) return;
    int orig = ((r & 3) << 11) + (r >> 2);
    o[r] = a[orig] + b[orig];
}

// ---------- mma + async helpers ----------
DEV_INLINE void mma16816h(float c[4], const uint32_t a[4], const uint32_t b[2]) {
    asm volatile(
        "mma.sync.aligned.m16n8k16.row.col.f32.f16.f16.f32 "
        "{%0,%1,%2,%3}, {%4,%5,%6,%7}, {%8,%9}, {%0,%1,%2,%3};\n"
        : "+f"(c[0]), "+f"(c[1]), "+f"(c[2]), "+f"(c[3])
        : "r"(a[0]), "r"(a[1]), "r"(a[2]), "r"(a[3]), "r"(b[0]), "r"(b[1]));
}

DEV_INLINE void cp_async16(__half* smem_ptr, const __half* gptr) {
    uint32_t s = (uint32_t)__cvta_generic_to_shared(smem_ptr);
    asm volatile("cp.async.cg.shared.global [%0], [%1], 16;\n" :: "r"(s), "l"(gptr));
}
DEV_INLINE void cp_commit() { asm volatile("cp.async.commit_group;\n" ::: "memory"); }
template <int N> DEV_INLINE void cp_wait() { asm volatile("cp.async.wait_group %0;\n" :: "n"(N) : "memory"); }

DEV_INLINE uint32_t s2u(const void* p) { return (uint32_t)__cvta_generic_to_shared(p); }

DEV_INLINE void mbar_init(uint32_t bar, uint32_t cnt) {
    asm volatile("mbarrier.init.shared.b64 [%0], %1;" :: "r"(bar), "r"(cnt) : "memory");
}
DEV_INLINE void mbar_expect_tx(uint32_t bar, uint32_t bytes) {
    asm volatile("mbarrier.arrive.expect_tx.shared.b64 _, [%0], %1;" :: "r"(bar), "r"(bytes) : "memory");
}
DEV_INLINE void mbar_wait(uint32_t bar, uint32_t parity) {
    asm volatile(
        "{\n\t.reg .pred P1;\n\t"
        "WL%=:\n\t"
        "mbarrier.try_wait.parity.shared.b64 P1, [%0], %1;\n\t"
        "@P1 bra.uni WD%=;\n\t"
        "bra.uni WL%=;\n\t"
        "WD%=:\n\t}"
        :: "r"(bar), "r"(parity) : "memory");
}
DEV_INLINE void bulk_cp(uint32_t dst_smem, const void* gsrc, uint32_t bytes, uint32_t bar) {
    asm volatile(
        "cp.async.bulk.shared::cta.global.mbarrier::complete_tx::bytes [%0], [%1], %2, [%3];"
        :: "r"(dst_smem), "l"(gsrc), "r"(bytes), "r"(bar) : "memory");
}

// ---------- pipelined fp16 GEMM (big input GEMM), unchanged ----------
template <int BM, int BN, int BK, int STAGES, int WROWS, int WCOLS, int WM, int WN>
__global__ void __launch_bounds__(WROWS * WCOLS * 32, 1)
gemm_pipe_kernel(const __half* __restrict__ A, const __half* __restrict__ B,
                 const float* __restrict__ addVec,
                 __half* __restrict__ Cout, int N, int K) {
    constexpr int NT = WROWS * WCOLS * 32;
    constexpr int LD = BK + 8, LD32 = LD / 2;
    constexpr int MI = WM / 16, NI = WN / 8;
    constexpr int A_ELE = BM * LD, B_ELE = BN * LD;
    constexpr int STAGE_ELE = A_ELE + B_ELE;

    extern __shared__ __half smem_g[];

    const int tid = threadIdx.x, wid = tid >> 5, lane = tid & 31;
    const int wrow = wid / WCOLS, wcol = wid % WCOLS;
    const int gl = lane >> 2, tig = lane & 3;
    const int bm = blockIdx.y * BM, bn = blockIdx.x * BN;
    const int KT = K / BK;

    float acc[MI][NI][4];
#pragma unroll
    for (int mi = 0; mi < MI; mi++)
#pragma unroll
        for (int ni = 0; ni < NI; ni++)
#pragma unroll
            for (int q = 0; q < 4; q++) acc[mi][ni][q] = 0.0f;

    auto load_stage = [&](int stg, int kt) {
        __half* sA = smem_g + stg * STAGE_ELE;
        __half* sB = sA + A_ELE;
        int k0 = kt * BK;
        for (int c = tid; c < BM * BK / 8; c += NT) {
            int r = c / (BK / 8), cc = (c % (BK / 8)) * 8;
            cp_async16(&sA[r * LD + cc], A + (size_t)(bm + r) * K + k0 + cc);
        }
        for (int c = tid; c < BN * BK / 8; c += NT) {
            int r = c / (BK / 8), cc = (c % (BK / 8)) * 8;
            cp_async16(&sB[r * LD + cc], B + (size_t)(bn + r) * K + k0 + cc);
        }
    };

#pragma unroll
    for (int s = 0; s < STAGES - 1; s++) {
        if (s < KT) load_stage(s, s);
        cp_commit();
    }

    for (int kt = 0; kt < KT; kt++) {
        cp_wait<STAGES - 2>();
        __syncthreads();
        int nk = kt + STAGES - 1;
        if (nk < KT) load_stage(nk % STAGES, nk);
        cp_commit();

        int stg = kt % STAGES;
        const uint32_t* A32 = reinterpret_cast<const uint32_t*>(smem_g + stg * STAGE_ELE);
        const uint32_t* B32 = A32 + A_ELE / 2;

#pragma unroll
        for (int ks = 0; ks < BK / 16; ks++) {
            uint32_t ah[MI][4];
#pragma unroll
            for (int mi = 0; mi < MI; mi++) {
                int r = wrow * WM + mi * 16 + gl;
                int p0 = r * LD32 + ks * 8 + tig, p1 = (r + 8) * LD32 + ks * 8 + tig;
                ah[mi][0] = A32[p0]; ah[mi][1] = A32[p1];
                ah[mi][2] = A32[p0 + 4]; ah[mi][3] = A32[p1 + 4];
            }
#pragma unroll
            for (int ni = 0; ni < NI; ni++) {
                int r = wcol * WN + ni * 8 + gl;
                int p = r * LD32 + ks * 8 + tig;
                uint32_t bh[2] = {B32[p], B32[p + 4]};
#pragma unroll
                for (int mi = 0; mi < MI; mi++) mma16816h(acc[mi][ni], ah[mi], bh);
            }
        }
    }

#pragma unroll
    for (int mi = 0; mi < MI; mi++) {
        int r0 = bm + wrow * WM + mi * 16 + gl, r1 = r0 + 8;
#pragma unroll
        for (int ni = 0; ni < NI; ni++) {
            int cb = bn + wcol * WN + ni * 8 + 2 * tig;
            float2 av = *reinterpret_cast<const float2*>(addVec + cb);
            __half2 h0 = __floats2half2_rn(acc[mi][ni][0] + av.x, acc[mi][ni][1] + av.y);
            __half2 h1 = __floats2half2_rn(acc[mi][ni][2] + av.x, acc[mi][ni][3] + av.y);
            *reinterpret_cast<__half2*>(Cout + (size_t)r0 * N + cb) = h0;
            *reinterpret_cast<__half2*>(Cout + (size_t)r1 * N + cb) = h1;
        }
    }
}

// ---------- fused step: bulk-copy pipeline + LSTM ----------
// smem stage: A (h) 64x128 halves (16KB) + B (W) 64x128 halves (16KB), both
// 16B-chunk swizzled: phys_chunk = chunk ^ (r&7). 3 stages = 96 KB.
constexpr int SSTG3 = 3;
constexpr int S_HALVES = 64 * 128;            // per operand per stage
constexpr int STAGE_HALVES = 2 * S_HALVES;    // 16384 halves = 32 KB
constexpr int SMEM_STEP = SSTG3 * STAGE_HALVES * 2;   // 98304 B
constexpr int SCLD = 68;

DEV_INLINE int swaddr(int r, int cb, int tig) {   // uint32 index in 64x128-half block
    return r * 64 + ((cb ^ (r & 7)) << 2) + tig;
}

__global__ void __launch_bounds__(128, 1)
step_fused_kernel(const __half* __restrict__ Hblk, const __half* __restrict__ Wblk,
                  const __half* __restrict__ xg_t,
                  const float* __restrict__ c_prev,
                  float* __restrict__ c_out, float* __restrict__ h_out,
                  __half* __restrict__ hblk_o, int first) {
    constexpr int MI = 2, NI = 4;
    extern __shared__ __half smem_s[];
    __shared__ __align__(8) uint64_t sbar[SSTG3];

    const int tid = threadIdx.x, wid = tid >> 5, lane = tid & 31;
    const int wrow = wid >> 1, wcol = wid & 1;
    const int gl = lane >> 2, tig = lane & 3;
    const int tile = blockIdx.x;
    const int bn = tile * 64;
    constexpr int KT = 16;

    float acc[MI][NI][4];
#pragma unroll
    for (int mi = 0; mi < MI; mi++)
#pragma unroll
        for (int ni = 0; ni < NI; ni++)
#pragma unroll
            for (int q = 0; q < 4; q++) acc[mi][ni][q] = 0.0f;

    if (!first) {
        if (tid == 0) {
#pragma unroll
            for (int s = 0; s < SSTG3; s++) mbar_init(s2u(&sbar[s]), 1);
        }
        __syncthreads();

        const uint32_t smem0 = s2u(smem_s);
        auto issue = [&](int stg, int kt) {
            uint32_t bar = s2u(&sbar[stg]);
            mbar_expect_tx(bar, 2 * S_HALVES * 2);
            bulk_cp(smem0 + stg * STAGE_HALVES * 2,
                    Hblk + (size_t)kt * S_HALVES, S_HALVES * 2, bar);
            bulk_cp(smem0 + stg * STAGE_HALVES * 2 + S_HALVES * 2,
                    Wblk + ((size_t)tile * 16 + kt) * S_HALVES, S_HALVES * 2, bar);
        };

        if (tid == 0) { issue(0, 0); issue(1, 1); }

        int ph[SSTG3] = {0, 0, 0};
        for (int kt = 0; kt < KT; kt++) {
            __syncthreads();                       // prior readers of stage (kt+2)%3 done
            int nk = kt + SSTG3 - 1;
            if (nk < KT && tid == 0) issue(nk % SSTG3, nk);

            int stg = kt % SSTG3;
            mbar_wait(s2u(&sbar[stg]), ph[stg]);
            ph[stg] ^= 1;

            const uint32_t* A32 = reinterpret_cast<const uint32_t*>(smem_s + stg * STAGE_HALVES);
            const uint32_t* B32 = A32 + S_HALVES / 2;

#pragma unroll
            for (int ks = 0; ks < 8; ks++) {
                uint32_t ah[MI][4];
#pragma unroll
                for (int mi = 0; mi < MI; mi++) {
                    int r = wrow * 32 + mi * 16 + gl;
                    ah[mi][0] = A32[swaddr(r,     2 * ks,     tig)];
                    ah[mi][1] = A32[swaddr(r + 8, 2 * ks,     tig)];
                    ah[mi][2] = A32[swaddr(r,     2 * ks + 1, tig)];
                    ah[mi][3] = A32[swaddr(r + 8, 2 * ks + 1, tig)];
                }
#pragma unroll
                for (int ni = 0; ni < NI; ni++) {
                    int r = wcol * 32 + ni * 8 + gl;
                    uint32_t bh[2] = {B32[swaddr(r, 2 * ks, tig)], B32[swaddr(r, 2 * ks + 1, tig)]};
#pragma unroll
                    for (int mi = 0; mi < MI; mi++) mma16816h(acc[mi][ni], ah[mi], bh);
                }
            }
        }
    }
    __syncthreads();

    // stage gates = acc + xg (fp16) into smem
    float* sC = reinterpret_cast<float*>(smem_s);   // [64][SCLD]
#pragma unroll
    for (int mi = 0; mi < MI; mi++) {
        int r0 = wrow * 32 + mi * 16 + gl, r1 = r0 + 8;
#pragma unroll
        for (int ni = 0; ni < NI; ni++) {
            int cb = wcol * 32 + ni * 8 + 2 * tig;
            float2 x0 = __half22float2(*reinterpret_cast<const __half2*>(xg_t + (size_t)r0 * Gg + bn + cb));
            float2 x1 = __half22float2(*reinterpret_cast<const __half2*>(xg_t + (size_t)r1 * Gg + bn + cb));
            sC[r0 * SCLD + cb]     = acc[mi][ni][0] + x0.x;
            sC[r0 * SCLD + cb + 1] = acc[mi][ni][1] + x0.y;
            sC[r1 * SCLD + cb]     = acc[mi][ni][2] + x1.x;
            sC[r1 * SCLD + cb + 1] = acc[mi][ni][3] + x1.y;
        }
    }
    __syncthreads();

    // LSTM elementwise: 1024 (batch, quad) pairs, 8 per thread
#pragma unroll
    for (int it = 0; it < 8; it++) {
        int pair = it * 128 + tid;
        int b = pair >> 4, qq = pair & 15;
        int jg = (bn >> 2) + qq;   // hidden unit index
        float gi = sC[b * SCLD + 4 * qq + 0];
        float gf = sC[b * SCLD + 4 * qq + 1];
        float gg = sC[b * SCLD + 4 * qq + 2];
        float go = sC[b * SCLD + 4 * qq + 3];
        float cp = first ? 0.0f : c_prev[b * Hh + jg];
        float si = 1.0f / (1.0f + expf(-gi));
        float sf = 1.0f / (1.0f + expf(-gf));
        float so = 1.0f / (1.0f + expf(-go));
        float cn = sf * cp + si * tanhf(gg);
        float hn = so * tanhf(cn);
        c_out[b * Hh + jg] = cn;
        h_out[b * Hh + jg] = hn;
        // blocked+swizzled h write: [kt][b][128] with chunk^=(b&7)
        int kt = jg >> 7, ch = jg & 127, chunk = ch >> 3;
        hblk_o[((size_t)kt * 64 + b) * 128 + ((chunk ^ (b & 7)) << 3) + (ch & 7)] = __float2half(hn);
    }
}

// ---------- batched projections + gumbel softmax ----------
__global__ void __launch_bounds__(256, 1)
proj_kernel(const float* __restrict__ hhist, const float* __restrict__ chist,
            const float* __restrict__ Wpred, const float* __restrict__ bpred,
            const float* __restrict__ Wpredc, const float* __restrict__ bpredc,
            const float* __restrict__ Wutil, const float* __restrict__ butil,
            const float* __restrict__ Wuse, const float* __restrict__ buse,
            const float* __restrict__ gum, float* __restrict__ out) {
    const int tb = blockIdx.x;
    const int t = tb >> 6;
    const int tid = threadIdx.x;
    const float* hr = hhist + (size_t)tb * Hh;
    const float* cr = chist + (size_t)tb * Hh;
    float v[7] = {0, 0, 0, 0, 0, 0, 0};

    for (int j = tid; j < Hh; j += 256) {
        float hn = hr[j], cn = cr[j];
        v[0] += hn * Wpred[j];       v[1] += hn * Wpred[Hh + j];
        v[2] += cn * Wpredc[j];      v[3] += cn * Wpredc[Hh + j];
        v[4] += hn * Wutil[j];
        v[5] += hn * Wuse[j];        v[6] += hn * Wuse[Hh + j];
    }
#pragma unroll
    for (int o = 16; o > 0; o >>= 1)
#pragma unroll
        for (int q = 0; q < 7; q++) v[q] += __shfl_xor_sync(0xffffffffu, v[q], o);

    __shared__ float red[8][7];
    int wid = tid >> 5, lane = tid & 31;
    if (lane == 0)
#pragma unroll
        for (int q = 0; q < 7; q++) red[wid][q] = v[q];
    __syncthreads();

    if (tid == 0) {
        float s[7];
#pragma unroll
        for (int q = 0; q < 7; q++) {
            float a = 0;
#pragma unroll
            for (int w = 0; w < 8; w++) a += red[w][q];
            s[q] = a;
        }
        out[OUT_H + tb * 2 + 0] = s[0] + bpred[0];
        out[OUT_H + tb * 2 + 1] = s[1] + bpred[1];
        out[OUT_C + tb * 2 + 0] = s[2] + bpredc[0];
        out[OUT_C + tb * 2 + 1] = s[3] + bpredc[1];
        out[OUT_U + tb] = s[4] + butil[0];
        float z0 = s[5] + buse[0] + gum[tb * 2 + 0];
        float z1 = s[6] + buse[1] + gum[tb * 2 + 1];
        float mz = fmaxf(z0, z1);
        float e0 = expf(z0 - mz), e1 = expf(z1 - mz);
        float inv = 1.0f / (e0 + e1);
        if (t >= 1) {
            int b = tb & 63;
            out[OUT_W + ((t - 1) * Bb + b) * 2 + 0] = e0 * inv;
            out[OUT_W + ((t - 1) * Bb + b) * 2 + 1] = e1 * inv;
        }
    }
}

// ---------- launch ----------
extern "C" void kernel_launch(void* const* d_in, const int* in_sizes, int n_in,
                              void* d_out, int out_size) {
    const float* feature = (const float*)d_in[0];
    const float* W_ih    = (const float*)d_in[1];
    const float* W_hh    = (const float*)d_in[2];
    const float* b_ih    = (const float*)d_in[3];
    const float* b_hh    = (const float*)d_in[4];
    const float* W_pred  = (const float*)d_in[5];
    const float* b_pred  = (const float*)d_in[6];
    const float* W_predc = (const float*)d_in[7];
    const float* b_predc = (const float*)d_in[8];
    const float* W_util  = (const float*)d_in[9];
    const float* b_util  = (const float*)d_in[10];
    const float* W_use   = (const float*)d_in[11];
    const float* b_use   = (const float*)d_in[12];
    float* out = (float*)d_out;

    void *p_f, *p_wih, *p_whh, *p_xg, *p_ch, *p_hh, *p_h16, *p_gum, *p_bias;
    cudaGetSymbolAddress(&p_f, g_featT);
    cudaGetSymbolAddress(&p_wih, g_wih);   cudaGetSymbolAddress(&p_whh, g_whh_blk);
    cudaGetSymbolAddress(&p_xg, g_xg);
    cudaGetSymbolAddress(&p_ch, g_chist);  cudaGetSymbolAddress(&p_hh, g_hhist);
    cudaGetSymbolAddress(&p_h16, g_h16blk);
    cudaGetSymbolAddress(&p_gum, g_gumbel); cudaGetSymbolAddress(&p_bias, g_bias);

    constexpr int SMEM_BIG = 4 * (128 * 72 + 128 * 72) * 2;   // 147456
    cudaFuncSetAttribute((const void*)gemm_pipe_kernel<128,128,64,4,2,4,64,32>,
                         cudaFuncAttributeMaxDynamicSharedMemorySize, SMEM_BIG);
    cudaFuncSetAttribute((const void*)step_fused_kernel,
                         cudaFuncAttributeMaxDynamicSharedMemorySize, SMEM_STEP);

    gumbel_kernel<<<48, 256>>>((float*)p_gum);
    bias_perm_kernel<<<(Gg + 255) / 256, 256>>>(b_ih, b_hh, (float*)p_bias);
    perm_h16_kernel<<<(Gg * Ff / 4 + 255) / 256, 256>>>(W_ih, (__half*)p_wih, Ff);
    perm_whh_blk_kernel<<<(128 * 16 * 64 * 16 + 255) / 256, 256>>>(W_hh, (__half*)p_whh);
    feat_prep_kernel<<<(M1 * Ff / 4 + 255) / 256, 256>>>(feature, (__half*)p_f);

    // xg = featT @ Wih_perm^T + bias_perm (permuted gate columns, fp16)
    gemm_pipe_kernel<128,128,64,4,2,4,64,32><<<dim3(Gg / 128, M1 / 128), 256, SMEM_BIG>>>(
        (const __half*)p_f, (const __half*)p_wih,
        (const float*)p_bias, (__half*)p_xg, Gg, Ff);

    for (int t = 0; t < Tt; t++) {
        step_fused_kernel<<<Gg / 64, 128, SMEM_STEP>>>(
            (const __half*)p_h16 + (size_t)((t + 1) & 1) * (16 * 64 * 128),  // read h(t-1)
            (const __half*)p_whh,
            (const __half*)p_xg + (size_t)t * Bb * Gg,
            (const float*)p_ch + (size_t)(t - 1) * Bb * Hh,
            (float*)p_ch + (size_t)t * Bb * Hh,
            (float*)p_hh + (size_t)t * Bb * Hh,
            (__half*)p_h16 + (size_t)(t & 1) * (16 * 64 * 128),              // write h(t)
            t == 0 ? 1 : 0);
    }

    proj_kernel<<<M1, 256>>>((const float*)p_hh, (const float*)p_ch,
                             W_pred, b_pred, W_predc, b_predc,
                             W_util, b_util, W_use, b_use,
                             (const float*)p_gum, out);
}

// round 16
// speedup vs baseline: 1.1737x; 1.0047x over previous
#include <cuda_runtime.h>
#include <cuda_fp16.h>
#include <cstdint>

#define DEV_INLINE __device__ __forceinline__

constexpr int Bb = 64, Tt = 96, Ff = 2048, Hh = 2048, Gg = 4 * Hh;
constexpr int M1 = Tt * Bb;                 // 6144

constexpr int OUT_H = 0;
constexpr int OUT_C = OUT_H + Tt * Bb * 2;
constexpr int OUT_U = OUT_C + Tt * Bb * 2;
constexpr int OUT_W = OUT_U + Tt * Bb;

__device__ __half g_featT[M1 * Ff];
__device__ __half g_wih[Gg * Ff];            // permuted rows (big GEMM)
__device__ __half g_whh_blk[Gg * Hh];        // blocked+swizzled [tile128][kt16][64][128]
__device__ __half g_xg[(size_t)M1 * Gg];     // permuted cols, fp16
__device__ float  g_chist[(size_t)M1 * Hh];
__device__ float  g_hhist[(size_t)M1 * Hh];
__device__ __half g_h16blk[2][16 * 64 * 128];// blocked+swizzled h, double buffer
__device__ float  g_gumbel[Tt * Bb * 2];
__device__ float  g_bias[Gg];                // permuted

// ---------- threefry2x32 gumbel, key=(0,42), partitionable counter scheme ----------
DEV_INLINE uint32_t rotl32(uint32_t x, int d) { return (x << d) | (x >> (32 - d)); }
DEV_INLINE void tfr(uint32_t& x0, uint32_t& x1, int r) { x0 += x1; x1 = rotl32(x1, r); x1 ^= x0; }

DEV_INLINE float bits_to_gumbel(uint32_t bits) {
    float u0 = __uint_as_float((bits >> 9) | 0x3f800000u) - 1.0f;
    const float tiny = 1.1754943508222875e-38f;
    float u = fmaxf(u0 * (1.0f - tiny) + tiny, tiny);
    return -logf(-logf(u));
}

__global__ void gumbel_kernel(float* __restrict__ out) {
    int i = blockIdx.x * blockDim.x + threadIdx.x;
    if (i >= Tt * Bb * 2) return;
    uint32_t x0 = 0u, x1 = (uint32_t)i;
    const uint32_t k0 = 0u, k1 = 42u, k2 = 0u ^ 42u ^ 0x1BD11BDAu;
    x0 += k0; x1 += k1;
    tfr(x0,x1,13); tfr(x0,x1,15); tfr(x0,x1,26); tfr(x0,x1,6);
    x0 += k1; x1 += k2 + 1u;
    tfr(x0,x1,17); tfr(x0,x1,29); tfr(x0,x1,16); tfr(x0,x1,24);
    x0 += k2; x1 += k0 + 2u;
    tfr(x0,x1,13); tfr(x0,x1,15); tfr(x0,x1,26); tfr(x0,x1,6);
    x0 += k0; x1 += k1 + 3u;
    tfr(x0,x1,17); tfr(x0,x1,29); tfr(x0,x1,16); tfr(x0,x1,24);
    x0 += k1; x1 += k2 + 4u;
    tfr(x0,x1,13); tfr(x0,x1,15); tfr(x0,x1,26); tfr(x0,x1,6);
    x0 += k2; x1 += k0 + 5u;
    out[i] = bits_to_gumbel(x0 ^ x1);
}

// ---------- fp32 -> fp16 prep ----------
DEV_INLINE void h4store(float4 v, __half* o) {
    __half2* o2 = reinterpret_cast<__half2*>(o);
    o2[0] = __floats2half2_rn(v.x, v.y);
    o2[1] = __floats2half2_rn(v.z, v.w);
}

__global__ void perm_h16_kernel(const float* __restrict__ in, __half* __restrict__ o, int K) {
    int i = blockIdx.x * blockDim.x + threadIdx.x;
    if (i >= Gg * K / 4) return;
    int e = i * 4;
    int r = e / K, k = e % K;
    int orig = ((r & 3) << 11) + (r >> 2);
    float4 v = *reinterpret_cast<const float4*>(in + (size_t)orig * K + k);
    h4store(v, o + (size_t)e);
}

// W_hh: permuted rows -> blocked [tile][kt][r][128] with 16B-chunk swizzle
__global__ void perm_whh_blk_kernel(const float* __restrict__ in, __half* __restrict__ o) {
    int i = blockIdx.x * blockDim.x + threadIdx.x;
    if (i >= 128 * 16 * 64 * 16) return;     // one 16B chunk (8 halves) per thread
    int chunk = i & 15;
    int r     = (i >> 4) & 63;
    int kt    = (i >> 10) & 15;
    int tile  = i >> 14;
    int pr = tile * 64 + r;
    int orig = ((pr & 3) << 11) + (pr >> 2);
    int k0 = kt * 128 + chunk * 8;
    const float* src = in + (size_t)orig * Hh + k0;
    float4 a = *reinterpret_cast<const float4*>(src);
    float4 b = *reinterpret_cast<const float4*>(src + 4);
    __half hh[8];
    hh[0]=__float2half(a.x); hh[1]=__float2half(a.y); hh[2]=__float2half(a.z); hh[3]=__float2half(a.w);
    hh[4]=__float2half(b.x); hh[5]=__float2half(b.y); hh[6]=__float2half(b.z); hh[7]=__float2half(b.w);
    size_t dst = ((size_t)(tile * 16 + kt) * 64 + r) * 128 + ((chunk ^ (r & 7)) << 3);
    *reinterpret_cast<uint4*>(o + dst) = *reinterpret_cast<uint4*>(hh);
}

__global__ void feat_prep_kernel(const float* __restrict__ feat, __half* __restrict__ o) {
    int i = blockIdx.x * blockDim.x + threadIdx.x;
    if (i >= (M1 * Ff) / 4) return;
    int e = i * 4, m = e >> 11, f = e & 2047, b = m & 63, t = m >> 6;
    float4 v = *reinterpret_cast<const float4*>(feat + ((size_t)b * Tt + t) * Ff + f);
    h4store(v, o + (size_t)e);
}

__global__ void bias_perm_kernel(const float* __restrict__ a, const float* __restrict__ b,
                                 float* __restrict__ o) {
    int r = blockIdx.x * blockDim.x + threadIdx.x;
    if (r >= Gg) return;
    int orig = ((r & 3) << 11) + (r >> 2);
    o[r] = a[orig] + b[orig];
}

// ---------- mma + async helpers ----------
DEV_INLINE void mma16816h(float c[4], const uint32_t a[4], const uint32_t b[2]) {
    asm volatile(
        "mma.sync.aligned.m16n8k16.row.col.f32.f16.f16.f32 "
        "{%0,%1,%2,%3}, {%4,%5,%6,%7}, {%8,%9}, {%0,%1,%2,%3};\n"
        : "+f"(c[0]), "+f"(c[1]), "+f"(c[2]), "+f"(c[3])
        : "r"(a[0]), "r"(a[1]), "r"(a[2]), "r"(a[3]), "r"(b[0]), "r"(b[1]));
}

DEV_INLINE void cp_async16(__half* smem_ptr, const __half* gptr) {
    uint32_t s = (uint32_t)__cvta_generic_to_shared(smem_ptr);
    asm volatile("cp.async.cg.shared.global [%0], [%1], 16;\n" :: "r"(s), "l"(gptr));
}
DEV_INLINE void cp_commit() { asm volatile("cp.async.commit_group;\n" ::: "memory"); }
template <int N> DEV_INLINE void cp_wait() { asm volatile("cp.async.wait_group %0;\n" :: "n"(N) : "memory"); }

DEV_INLINE uint32_t s2u(const void* p) { return (uint32_t)__cvta_generic_to_shared(p); }

DEV_INLINE void mbar_init(uint32_t bar, uint32_t cnt) {
    asm volatile("mbarrier.init.shared.b64 [%0], %1;" :: "r"(bar), "r"(cnt) : "memory");
}
DEV_INLINE void mbar_expect_tx(uint32_t bar, uint32_t bytes) {
    asm volatile("mbarrier.arrive.expect_tx.shared.b64 _, [%0], %1;" :: "r"(bar), "r"(bytes) : "memory");
}
DEV_INLINE void mbar_wait(uint32_t bar, uint32_t parity) {
    asm volatile(
        "{\n\t.reg .pred P1;\n\t"
        "WL%=:\n\t"
        "mbarrier.try_wait.parity.shared.b64 P1, [%0], %1;\n\t"
        "@P1 bra.uni WD%=;\n\t"
        "bra.uni WL%=;\n\t"
        "WD%=:\n\t}"
        :: "r"(bar), "r"(parity) : "memory");
}
DEV_INLINE void bulk_cp(uint32_t dst_smem, const void* gsrc, uint32_t bytes, uint32_t bar) {
    asm volatile(
        "cp.async.bulk.shared::cta.global.mbarrier::complete_tx::bytes [%0], [%1], %2, [%3];"
        :: "r"(dst_smem), "l"(gsrc), "r"(bytes), "r"(bar) : "memory");
}

// ---------- pipelined fp16 GEMM (big input GEMM), unchanged ----------
template <int BM, int BN, int BK, int STAGES, int WROWS, int WCOLS, int WM, int WN>
__global__ void __launch_bounds__(WROWS * WCOLS * 32, 1)
gemm_pipe_kernel(const __half* __restrict__ A, const __half* __restrict__ B,
                 const float* __restrict__ addVec,
                 __half* __restrict__ Cout, int N, int K) {
    constexpr int NT = WROWS * WCOLS * 32;
    constexpr int LD = BK + 8, LD32 = LD / 2;
    constexpr int MI = WM / 16, NI = WN / 8;
    constexpr int A_ELE = BM * LD, B_ELE = BN * LD;
    constexpr int STAGE_ELE = A_ELE + B_ELE;

    extern __shared__ __half smem_g[];

    const int tid = threadIdx.x, wid = tid >> 5, lane = tid & 31;
    const int wrow = wid / WCOLS, wcol = wid % WCOLS;
    const int gl = lane >> 2, tig = lane & 3;
    const int bm = blockIdx.y * BM, bn = blockIdx.x * BN;
    const int KT = K / BK;

    float acc[MI][NI][4];
#pragma unroll
    for (int mi = 0; mi < MI; mi++)
#pragma unroll
        for (int ni = 0; ni < NI; ni++)
#pragma unroll
            for (int q = 0; q < 4; q++) acc[mi][ni][q] = 0.0f;

    auto load_stage = [&](int stg, int kt) {
        __half* sA = smem_g + stg * STAGE_ELE;
        __half* sB = sA + A_ELE;
        int k0 = kt * BK;
        for (int c = tid; c < BM * BK / 8; c += NT) {
            int r = c / (BK / 8), cc = (c % (BK / 8)) * 8;
            cp_async16(&sA[r * LD + cc], A + (size_t)(bm + r) * K + k0 + cc);
        }
        for (int c = tid; c < BN * BK / 8; c += NT) {
            int r = c / (BK / 8), cc = (c % (BK / 8)) * 8;
            cp_async16(&sB[r * LD + cc], B + (size_t)(bn + r) * K + k0 + cc);
        }
    };

#pragma unroll
    for (int s = 0; s < STAGES - 1; s++) {
        if (s < KT) load_stage(s, s);
        cp_commit();
    }

    for (int kt = 0; kt < KT; kt++) {
        cp_wait<STAGES - 2>();
        __syncthreads();
        int nk = kt + STAGES - 1;
        if (nk < KT) load_stage(nk % STAGES, nk);
        cp_commit();

        int stg = kt % STAGES;
        const uint32_t* A32 = reinterpret_cast<const uint32_t*>(smem_g + stg * STAGE_ELE);
        const uint32_t* B32 = A32 + A_ELE / 2;

#pragma unroll
        for (int ks = 0; ks < BK / 16; ks++) {
            uint32_t ah[MI][4];
#pragma unroll
            for (int mi = 0; mi < MI; mi++) {
                int r = wrow * WM + mi * 16 + gl;
                int p0 = r * LD32 + ks * 8 + tig, p1 = (r + 8) * LD32 + ks * 8 + tig;
                ah[mi][0] = A32[p0]; ah[mi][1] = A32[p1];
                ah[mi][2] = A32[p0 + 4]; ah[mi][3] = A32[p1 + 4];
            }
#pragma unroll
            for (int ni = 0; ni < NI; ni++) {
                int r = wcol * WN + ni * 8 + gl;
                int p = r * LD32 + ks * 8 + tig;
                uint32_t bh[2] = {B32[p], B32[p + 4]};
#pragma unroll
                for (int mi = 0; mi < MI; mi++) mma16816h(acc[mi][ni], ah[mi], bh);
            }
        }
    }

#pragma unroll
    for (int mi = 0; mi < MI; mi++) {
        int r0 = bm + wrow * WM + mi * 16 + gl, r1 = r0 + 8;
#pragma unroll
        for (int ni = 0; ni < NI; ni++) {
            int cb = bn + wcol * WN + ni * 8 + 2 * tig;
            float2 av = *reinterpret_cast<const float2*>(addVec + cb);
            __half2 h0 = __floats2half2_rn(acc[mi][ni][0] + av.x, acc[mi][ni][1] + av.y);
            __half2 h1 = __floats2half2_rn(acc[mi][ni][2] + av.x, acc[mi][ni][3] + av.y);
            *reinterpret_cast<__half2*>(Cout + (size_t)r0 * N + cb) = h0;
            *reinterpret_cast<__half2*>(Cout + (size_t)r1 * N + cb) = h1;
        }
    }
}

// ---------- fused step: bulk-copy pipeline + LSTM (256 thr, 4x2 warps, MI=1 NI=4) ----------
constexpr int SSTG4 = 4;
constexpr int S_HALVES = 64 * 128;            // per operand per stage
constexpr int STAGE_HALVES = 2 * S_HALVES;    // 16384 halves = 32 KB
constexpr int SMEM_STEP = SSTG4 * STAGE_HALVES * 2;   // 131072 B
constexpr int SCLD = 68;

DEV_INLINE int swaddr(int r, int cb, int tig) {   // uint32 index in 64x128-half block
    return r * 64 + ((cb ^ (r & 7)) << 2) + tig;
}

__global__ void __launch_bounds__(256, 1)
step_fused_kernel(const __half* __restrict__ Hblk, const __half* __restrict__ Wblk,
                  const __half* __restrict__ xg_t,
                  const float* __restrict__ c_prev,
                  float* __restrict__ c_out, float* __restrict__ h_out,
                  __half* __restrict__ hblk_o, int first) {
    constexpr int NI = 4;
    extern __shared__ __half smem_s[];
    __shared__ __align__(8) uint64_t sbar[SSTG4];

    const int tid = threadIdx.x, wid = tid >> 5, lane = tid & 31;
    const int wrow = wid >> 1, wcol = wid & 1;   // 4 x 2 warps
    const int gl = lane >> 2, tig = lane & 3;
    const int tile = blockIdx.x;
    const int bn = tile * 64;
    constexpr int KT = 16;

    float acc[NI][4];
#pragma unroll
    for (int ni = 0; ni < NI; ni++)
#pragma unroll
        for (int q = 0; q < 4; q++) acc[ni][q] = 0.0f;

    if (!first) {
        if (tid == 0) {
#pragma unroll
            for (int s = 0; s < SSTG4; s++) mbar_init(s2u(&sbar[s]), 1);
        }
        __syncthreads();

        const uint32_t smem0 = s2u(smem_s);
        auto issue = [&](int stg, int kt) {
            uint32_t bar = s2u(&sbar[stg]);
            mbar_expect_tx(bar, 2 * S_HALVES * 2);
            bulk_cp(smem0 + stg * STAGE_HALVES * 2,
                    Hblk + (size_t)kt * S_HALVES, S_HALVES * 2, bar);
            bulk_cp(smem0 + stg * STAGE_HALVES * 2 + S_HALVES * 2,
                    Wblk + ((size_t)tile * 16 + kt) * S_HALVES, S_HALVES * 2, bar);
        };

        if (tid == 0) { issue(0, 0); issue(1, 1); issue(2, 2); }

        int ph[SSTG4] = {0, 0, 0, 0};
        for (int kt = 0; kt < KT; kt++) {
            __syncthreads();                       // prior readers of reused stage done
            int nk = kt + SSTG4 - 1;
            if (nk < KT && tid == 0) issue(nk % SSTG4, nk);

            int stg = kt % SSTG4;
            mbar_wait(s2u(&sbar[stg]), ph[stg]);
            ph[stg] ^= 1;

            const uint32_t* A32 = reinterpret_cast<const uint32_t*>(smem_s + stg * STAGE_HALVES);
            const uint32_t* B32 = A32 + S_HALVES / 2;

#pragma unroll
            for (int ks = 0; ks < 8; ks++) {
                uint32_t ah[4];
                {
                    int r = wrow * 16 + gl;
                    ah[0] = A32[swaddr(r,     2 * ks,     tig)];
                    ah[1] = A32[swaddr(r + 8, 2 * ks,     tig)];
                    ah[2] = A32[swaddr(r,     2 * ks + 1, tig)];
                    ah[3] = A32[swaddr(r + 8, 2 * ks + 1, tig)];
                }
#pragma unroll
                for (int ni = 0; ni < NI; ni++) {
                    int r = wcol * 32 + ni * 8 + gl;
                    uint32_t bh[2] = {B32[swaddr(r, 2 * ks, tig)], B32[swaddr(r, 2 * ks + 1, tig)]};
                    mma16816h(acc[ni], ah, bh);
                }
            }
        }
    }
    __syncthreads();

    // stage gates = acc + xg (fp16) into smem
    float* sC = reinterpret_cast<float*>(smem_s);   // [64][SCLD]
    {
        int r0 = wrow * 16 + gl, r1 = r0 + 8;
#pragma unroll
        for (int ni = 0; ni < NI; ni++) {
            int cb = wcol * 32 + ni * 8 + 2 * tig;
            float2 x0 = __half22float2(*reinterpret_cast<const __half2*>(xg_t + (size_t)r0 * Gg + bn + cb));
            float2 x1 = __half22float2(*reinterpret_cast<const __half2*>(xg_t + (size_t)r1 * Gg + bn + cb));
            sC[r0 * SCLD + cb]     = acc[ni][0] + x0.x;
            sC[r0 * SCLD + cb + 1] = acc[ni][1] + x0.y;
            sC[r1 * SCLD + cb]     = acc[ni][2] + x1.x;
            sC[r1 * SCLD + cb + 1] = acc[ni][3] + x1.y;
        }
    }
    __syncthreads();

    // LSTM elementwise: 1024 (batch, quad) pairs, 4 per thread
#pragma unroll
    for (int it = 0; it < 4; it++) {
        int pair = it * 256 + tid;
        int b = pair >> 4, qq = pair & 15;
        int jg = (bn >> 2) + qq;   // hidden unit index
        float gi = sC[b * SCLD + 4 * qq + 0];
        float gf = sC[b * SCLD + 4 * qq + 1];
        float gg = sC[b * SCLD + 4 * qq + 2];
        float go = sC[b * SCLD + 4 * qq + 3];
        float cp = first ? 0.0f : c_prev[b * Hh + jg];
        float si = 1.0f / (1.0f + expf(-gi));
        float sf = 1.0f / (1.0f + expf(-gf));
        float so = 1.0f / (1.0f + expf(-go));
        float cn = sf * cp + si * tanhf(gg);
        float hn = so * tanhf(cn);
        c_out[b * Hh + jg] = cn;
        h_out[b * Hh + jg] = hn;
        int kt = jg >> 7, ch = jg & 127, chunk = ch >> 3;
        hblk_o[((size_t)kt * 64 + b) * 128 + ((chunk ^ (b & 7)) << 3) + (ch & 7)] = __float2half(hn);
    }
}

// ---------- batched projections + gumbel softmax ----------
__global__ void __launch_bounds__(256, 1)
proj_kernel(const float* __restrict__ hhist, const float* __restrict__ chist,
            const float* __restrict__ Wpred, const float* __restrict__ bpred,
            const float* __restrict__ Wpredc, const float* __restrict__ bpredc,
            const float* __restrict__ Wutil, const float* __restrict__ butil,
            const float* __restrict__ Wuse, const float* __restrict__ buse,
            const float* __restrict__ gum, float* __restrict__ out) {
    const int tb = blockIdx.x;
    const int t = tb >> 6;
    const int tid = threadIdx.x;
    const float* hr = hhist + (size_t)tb * Hh;
    const float* cr = chist + (size_t)tb * Hh;
    float v[7] = {0, 0, 0, 0, 0, 0, 0};

    for (int j = tid; j < Hh; j += 256) {
        float hn = hr[j], cn = cr[j];
        v[0] += hn * Wpred[j];       v[1] += hn * Wpred[Hh + j];
        v[2] += cn * Wpredc[j];      v[3] += cn * Wpredc[Hh + j];
        v[4] += hn * Wutil[j];
        v[5] += hn * Wuse[j];        v[6] += hn * Wuse[Hh + j];
    }
#pragma unroll
    for (int o = 16; o > 0; o >>= 1)
#pragma unroll
        for (int q = 0; q < 7; q++) v[q] += __shfl_xor_sync(0xffffffffu, v[q], o);

    __shared__ float red[8][7];
    int wid = tid >> 5, lane = tid & 31;
    if (lane == 0)
#pragma unroll
        for (int q = 0; q < 7; q++) red[wid][q] = v[q];
    __syncthreads();

    if (tid == 0) {
        float s[7];
#pragma unroll
        for (int q = 0; q < 7; q++) {
            float a = 0;
#pragma unroll
            for (int w = 0; w < 8; w++) a += red[w][q];
            s[q] = a;
        }
        out[OUT_H + tb * 2 + 0] = s[0] + bpred[0];
        out[OUT_H + tb * 2 + 1] = s[1] + bpred[1];
        out[OUT_C + tb * 2 + 0] = s[2] + bpredc[0];
        out[OUT_C + tb * 2 + 1] = s[3] + bpredc[1];
        out[OUT_U + tb] = s[4] + butil[0];
        float z0 = s[5] + buse[0] + gum[tb * 2 + 0];
        float z1 = s[6] + buse[1] + gum[tb * 2 + 1];
        float mz = fmaxf(z0, z1);
        float e0 = expf(z0 - mz), e1 = expf(z1 - mz);
        float inv = 1.0f / (e0 + e1);
        if (t >= 1) {
            int b = tb & 63;
            out[OUT_W + ((t - 1) * Bb + b) * 2 + 0] = e0 * inv;
            out[OUT_W + ((t - 1) * Bb + b) * 2 + 1] = e1 * inv;
        }
    }
}

// ---------- launch ----------
extern "C" void kernel_launch(void* const* d_in, const int* in_sizes, int n_in,
                              void* d_out, int out_size) {
    const float* feature = (const float*)d_in[0];
    const float* W_ih    = (const float*)d_in[1];
    const float* W_hh    = (const float*)d_in[2];
    const float* b_ih    = (const float*)d_in[3];
    const float* b_hh    = (const float*)d_in[4];
    const float* W_pred  = (const float*)d_in[5];
    const float* b_pred  = (const float*)d_in[6];
    const float* W_predc = (const float*)d_in[7];
    const float* b_predc = (const float*)d_in[8];
    const float* W_util  = (const float*)d_in[9];
    const float* b_util  = (const float*)d_in[10];
    const float* W_use   = (const float*)d_in[11];
    const float* b_use   = (const float*)d_in[12];
    float* out = (float*)d_out;

    void *p_f, *p_wih, *p_whh, *p_xg, *p_ch, *p_hh, *p_h16, *p_gum, *p_bias;
    cudaGetSymbolAddress(&p_f, g_featT);
    cudaGetSymbolAddress(&p_wih, g_wih);   cudaGetSymbolAddress(&p_whh, g_whh_blk);
    cudaGetSymbolAddress(&p_xg, g_xg);
    cudaGetSymbolAddress(&p_ch, g_chist);  cudaGetSymbolAddress(&p_hh, g_hhist);
    cudaGetSymbolAddress(&p_h16, g_h16blk);
    cudaGetSymbolAddress(&p_gum, g_gumbel); cudaGetSymbolAddress(&p_bias, g_bias);

    constexpr int SMEM_BIG = 4 * (128 * 72 + 128 * 72) * 2;   // 147456
    cudaFuncSetAttribute((const void*)gemm_pipe_kernel<128,128,64,4,2,4,64,32>,
                         cudaFuncAttributeMaxDynamicSharedMemorySize, SMEM_BIG);
    cudaFuncSetAttribute((const void*)step_fused_kernel,
                         cudaFuncAttributeMaxDynamicSharedMemorySize, SMEM_STEP);

    gumbel_kernel<<<48, 256>>>((float*)p_gum);
    bias_perm_kernel<<<(Gg + 255) / 256, 256>>>(b_ih, b_hh, (float*)p_bias);
    perm_h16_kernel<<<(Gg * Ff / 4 + 255) / 256, 256>>>(W_ih, (__half*)p_wih, Ff);
    perm_whh_blk_kernel<<<(128 * 16 * 64 * 16 + 255) / 256, 256>>>(W_hh, (__half*)p_whh);
    feat_prep_kernel<<<(M1 * Ff / 4 + 255) / 256, 256>>>(feature, (__half*)p_f);

    // xg = featT @ Wih_perm^T + bias_perm (permuted gate columns, fp16)
    gemm_pipe_kernel<128,128,64,4,2,4,64,32><<<dim3(Gg / 128, M1 / 128), 256, SMEM_BIG>>>(
        (const __half*)p_f, (const __half*)p_wih,
        (const float*)p_bias, (__half*)p_xg, Gg, Ff);

    for (int t = 0; t < Tt; t++) {
        step_fused_kernel<<<Gg / 64, 256, SMEM_STEP>>>(
            (const __half*)p_h16 + (size_t)((t + 1) & 1) * (16 * 64 * 128),  // read h(t-1)
            (const __half*)p_whh,
            (const __half*)p_xg + (size_t)t * Bb * Gg,
            (const float*)p_ch + (size_t)(t - 1) * Bb * Hh,
            (float*)p_ch + (size_t)t * Bb * Hh,
            (float*)p_hh + (size_t)t * Bb * Hh,
            (__half*)p_h16 + (size_t)(t & 1) * (16 * 64 * 128),              // write h(t)
            t == 0 ? 1 : 0);
    }

    proj_kernel<<<M1, 256>>>((const float*)p_hh, (const float*)p_ch,
                             W_pred, b_pred, W_predc, b_predc,
                             W_util, b_util, W_use, b_use,
                             (const float*)p_gum, out);
}

// round 17
// speedup vs baseline: 1.2809x; 1.0913x over previous
#include <cuda_runtime.h>
#include <cuda_fp16.h>
#include <cstdint>

#define DEV_INLINE __device__ __forceinline__

constexpr int Bb = 64, Tt = 96, Ff = 2048, Hh = 2048, Gg = 4 * Hh;
constexpr int M1 = Tt * Bb;                 // 6144

constexpr int OUT_H = 0;
constexpr int OUT_C = OUT_H + Tt * Bb * 2;
constexpr int OUT_U = OUT_C + Tt * Bb * 2;
constexpr int OUT_W = OUT_U + Tt * Bb;

__device__ __half g_featT[M1 * Ff];
__device__ __half g_wih[Gg * Ff];            // permuted rows (big GEMM)
__device__ __half g_whh_blk[Gg * Hh];        // blocked+swizzled [tile128][kt16][64][128]
__device__ __half g_xg[(size_t)M1 * Gg];     // permuted cols, fp16
__device__ float  g_chist[(size_t)M1 * Hh];
__device__ float  g_hhist[(size_t)M1 * Hh];
__device__ __half g_h16blk[2][16 * 64 * 128];// blocked+swizzled h, double buffer
__device__ float  g_gumbel[Tt * Bb * 2];
__device__ float  g_bias[Gg];                // permuted
__device__ unsigned g_barctr;

// ---------- threefry2x32 gumbel, key=(0,42), partitionable counter scheme ----------
DEV_INLINE uint32_t rotl32(uint32_t x, int d) { return (x << d) | (x >> (32 - d)); }
DEV_INLINE void tfr(uint32_t& x0, uint32_t& x1, int r) { x0 += x1; x1 = rotl32(x1, r); x1 ^= x0; }

DEV_INLINE float bits_to_gumbel(uint32_t bits) {
    float u0 = __uint_as_float((bits >> 9) | 0x3f800000u) - 1.0f;
    const float tiny = 1.1754943508222875e-38f;
    float u = fmaxf(u0 * (1.0f - tiny) + tiny, tiny);
    return -logf(-logf(u));
}

__global__ void gumbel_kernel(float* __restrict__ out, unsigned* __restrict__ barctr) {
    int i = blockIdx.x * blockDim.x + threadIdx.x;
    if (i == 0) *barctr = 0u;
    if (i >= Tt * Bb * 2) return;
    uint32_t x0 = 0u, x1 = (uint32_t)i;
    const uint32_t k0 = 0u, k1 = 42u, k2 = 0u ^ 42u ^ 0x1BD11BDAu;
    x0 += k0; x1 += k1;
    tfr(x0,x1,13); tfr(x0,x1,15); tfr(x0,x1,26); tfr(x0,x1,6);
    x0 += k1; x1 += k2 + 1u;
    tfr(x0,x1,17); tfr(x0,x1,29); tfr(x0,x1,16); tfr(x0,x1,24);
    x0 += k2; x1 += k0 + 2u;
    tfr(x0,x1,13); tfr(x0,x1,15); tfr(x0,x1,26); tfr(x0,x1,6);
    x0 += k0; x1 += k1 + 3u;
    tfr(x0,x1,17); tfr(x0,x1,29); tfr(x0,x1,16); tfr(x0,x1,24);
    x0 += k1; x1 += k2 + 4u;
    tfr(x0,x1,13); tfr(x0,x1,15); tfr(x0,x1,26); tfr(x0,x1,6);
    x0 += k2; x1 += k0 + 5u;
    out[i] = bits_to_gumbel(x0 ^ x1);
}

// ---------- fp32 -> fp16 prep ----------
DEV_INLINE void h4store(float4 v, __half* o) {
    __half2* o2 = reinterpret_cast<__half2*>(o);
    o2[0] = __floats2half2_rn(v.x, v.y);
    o2[1] = __floats2half2_rn(v.z, v.w);
}

__global__ void perm_h16_kernel(const float* __restrict__ in, __half* __restrict__ o, int K) {
    int i = blockIdx.x * blockDim.x + threadIdx.x;
    if (i >= Gg * K / 4) return;
    int e = i * 4;
    int r = e / K, k = e % K;
    int orig = ((r & 3) << 11) + (r >> 2);
    float4 v = *reinterpret_cast<const float4*>(in + (size_t)orig * K + k);
    h4store(v, o + (size_t)e);
}

// W_hh: permuted rows -> blocked [tile][kt][r][128] with 16B-chunk swizzle
__global__ void perm_whh_blk_kernel(const float* __restrict__ in, __half* __restrict__ o) {
    int i = blockIdx.x * blockDim.x + threadIdx.x;
    if (i >= 128 * 16 * 64 * 16) return;
    int chunk = i & 15;
    int r     = (i >> 4) & 63;
    int kt    = (i >> 10) & 15;
    int tile  = i >> 14;
    int pr = tile * 64 + r;
    int orig = ((pr & 3) << 11) + (pr >> 2);
    int k0 = kt * 128 + chunk * 8;
    const float* src = in + (size_t)orig * Hh + k0;
    float4 a = *reinterpret_cast<const float4*>(src);
    float4 b = *reinterpret_cast<const float4*>(src + 4);
    __half hh[8];
    hh[0]=__float2half(a.x); hh[1]=__float2half(a.y); hh[2]=__float2half(a.z); hh[3]=__float2half(a.w);
    hh[4]=__float2half(b.x); hh[5]=__float2half(b.y); hh[6]=__float2half(b.z); hh[7]=__float2half(b.w);
    size_t dst = ((size_t)(tile * 16 + kt) * 64 + r) * 128 + ((chunk ^ (r & 7)) << 3);
    *reinterpret_cast<uint4*>(o + dst) = *reinterpret_cast<uint4*>(hh);
}

__global__ void feat_prep_kernel(const float* __restrict__ feat, __half* __restrict__ o) {
    int i = blockIdx.x * blockDim.x + threadIdx.x;
    if (i >= (M1 * Ff) / 4) return;
    int e = i * 4, m = e >> 11, f = e & 2047, b = m & 63, t = m >> 6;
    float4 v = *reinterpret_cast<const float4*>(feat + ((size_t)b * Tt + t) * Ff + f);
    h4store(v, o + (size_t)e);
}

__global__ void bias_perm_kernel(const float* __restrict__ a, const float* __restrict__ b,
                                 float* __restrict__ o) {
    int r = blockIdx.x * blockDim.x + threadIdx.x;
    if (r >= Gg) return;
    int orig = ((r & 3) << 11) + (r >> 2);
    o[r] = a[orig] + b[orig];
}

// ---------- mma + async helpers ----------
DEV_INLINE void mma16816h(float c[4], const uint32_t a[4], const uint32_t b[2]) {
    asm volatile(
        "mma.sync.aligned.m16n8k16.row.col.f32.f16.f16.f32 "
        "{%0,%1,%2,%3}, {%4,%5,%6,%7}, {%8,%9}, {%0,%1,%2,%3};\n"
        : "+f"(c[0]), "+f"(c[1]), "+f"(c[2]), "+f"(c[3])
        : "r"(a[0]), "r"(a[1]), "r"(a[2]), "r"(a[3]), "r"(b[0]), "r"(b[1]));
}

DEV_INLINE void cp_async16(__half* smem_ptr, const __half* gptr) {
    uint32_t s = (uint32_t)__cvta_generic_to_shared(smem_ptr);
    asm volatile("cp.async.cg.shared.global [%0], [%1], 16;\n" :: "r"(s), "l"(gptr));
}
DEV_INLINE void cp_commit() { asm volatile("cp.async.commit_group;\n" ::: "memory"); }
template <int N> DEV_INLINE void cp_wait() { asm volatile("cp.async.wait_group %0;\n" :: "n"(N) : "memory"); }

DEV_INLINE uint32_t s2u(const void* p) { return (uint32_t)__cvta_generic_to_shared(p); }

DEV_INLINE void mbar_init(uint32_t bar, uint32_t cnt) {
    asm volatile("mbarrier.init.shared.b64 [%0], %1;" :: "r"(bar), "r"(cnt) : "memory");
}
DEV_INLINE void mbar_expect_tx(uint32_t bar, uint32_t bytes) {
    asm volatile("mbarrier.arrive.expect_tx.shared.b64 _, [%0], %1;" :: "r"(bar), "r"(bytes) : "memory");
}
DEV_INLINE void mbar_wait(uint32_t bar, uint32_t parity) {
    asm volatile(
        "{\n\t.reg .pred P1;\n\t"
        "WL%=:\n\t"
        "mbarrier.try_wait.parity.shared.b64 P1, [%0], %1;\n\t"
        "@P1 bra.uni WD%=;\n\t"
        "bra.uni WL%=;\n\t"
        "WD%=:\n\t}"
        :: "r"(bar), "r"(parity) : "memory");
}
DEV_INLINE void bulk_cp(uint32_t dst_smem, const void* gsrc, uint32_t bytes, uint32_t bar) {
    asm volatile(
        "cp.async.bulk.shared::cta.global.mbarrier::complete_tx::bytes [%0], [%1], %2, [%3];"
        :: "r"(dst_smem), "l"(gsrc), "r"(bytes), "r"(bar) : "memory");
}

// ---------- pipelined fp16 GEMM (big input GEMM), unchanged ----------
template <int BM, int BN, int BK, int STAGES, int WROWS, int WCOLS, int WM, int WN>
__global__ void __launch_bounds__(WROWS * WCOLS * 32, 1)
gemm_pipe_kernel(const __half* __restrict__ A, const __half* __restrict__ B,
                 const float* __restrict__ addVec,
                 __half* __restrict__ Cout, int N, int K) {
    constexpr int NT = WROWS * WCOLS * 32;
    constexpr int LD = BK + 8, LD32 = LD / 2;
    constexpr int MI = WM / 16, NI = WN / 8;
    constexpr int A_ELE = BM * LD, B_ELE = BN * LD;
    constexpr int STAGE_ELE = A_ELE + B_ELE;

    extern __shared__ __half smem_g[];

    const int tid = threadIdx.x, wid = tid >> 5, lane = tid & 31;
    const int wrow = wid / WCOLS, wcol = wid % WCOLS;
    const int gl = lane >> 2, tig = lane & 3;
    const int bm = blockIdx.y * BM, bn = blockIdx.x * BN;
    const int KT = K / BK;

    float acc[MI][NI][4];
#pragma unroll
    for (int mi = 0; mi < MI; mi++)
#pragma unroll
        for (int ni = 0; ni < NI; ni++)
#pragma unroll
            for (int q = 0; q < 4; q++) acc[mi][ni][q] = 0.0f;

    auto load_stage = [&](int stg, int kt) {
        __half* sA = smem_g + stg * STAGE_ELE;
        __half* sB = sA + A_ELE;
        int k0 = kt * BK;
        for (int c = tid; c < BM * BK / 8; c += NT) {
            int r = c / (BK / 8), cc = (c % (BK / 8)) * 8;
            cp_async16(&sA[r * LD + cc], A + (size_t)(bm + r) * K + k0 + cc);
        }
        for (int c = tid; c < BN * BK / 8; c += NT) {
            int r = c / (BK / 8), cc = (c % (BK / 8)) * 8;
            cp_async16(&sB[r * LD + cc], B + (size_t)(bn + r) * K + k0 + cc);
        }
    };

#pragma unroll
    for (int s = 0; s < STAGES - 1; s++) {
        if (s < KT) load_stage(s, s);
        cp_commit();
    }

    for (int kt = 0; kt < KT; kt++) {
        cp_wait<STAGES - 2>();
        __syncthreads();
        int nk = kt + STAGES - 1;
        if (nk < KT) load_stage(nk % STAGES, nk);
        cp_commit();

        int stg = kt % STAGES;
        const uint32_t* A32 = reinterpret_cast<const uint32_t*>(smem_g + stg * STAGE_ELE);
        const uint32_t* B32 = A32 + A_ELE / 2;

#pragma unroll
        for (int ks = 0; ks < BK / 16; ks++) {
            uint32_t ah[MI][4];
#pragma unroll
            for (int mi = 0; mi < MI; mi++) {
                int r = wrow * WM + mi * 16 + gl;
                int p0 = r * LD32 + ks * 8 + tig, p1 = (r + 8) * LD32 + ks * 8 + tig;
                ah[mi][0] = A32[p0]; ah[mi][1] = A32[p1];
                ah[mi][2] = A32[p0 + 4]; ah[mi][3] = A32[p1 + 4];
            }
#pragma unroll
            for (int ni = 0; ni < NI; ni++) {
                int r = wcol * WN + ni * 8 + gl;
                int p = r * LD32 + ks * 8 + tig;
                uint32_t bh[2] = {B32[p], B32[p + 4]};
#pragma unroll
                for (int mi = 0; mi < MI; mi++) mma16816h(acc[mi][ni], ah[mi], bh);
            }
        }
    }

#pragma unroll
    for (int mi = 0; mi < MI; mi++) {
        int r0 = bm + wrow * WM + mi * 16 + gl, r1 = r0 + 8;
#pragma unroll
        for (int ni = 0; ni < NI; ni++) {
            int cb = bn + wcol * WN + ni * 8 + 2 * tig;
            float2 av = *reinterpret_cast<const float2*>(addVec + cb);
            __half2 h0 = __floats2half2_rn(acc[mi][ni][0] + av.x, acc[mi][ni][1] + av.y);
            __half2 h1 = __floats2half2_rn(acc[mi][ni][2] + av.x, acc[mi][ni][3] + av.y);
            *reinterpret_cast<__half2*>(Cout + (size_t)r0 * N + cb) = h0;
            *reinterpret_cast<__half2*>(Cout + (size_t)r1 * N + cb) = h1;
        }
    }
}

// ---------- persistent recurrence: bulk pipeline + split W/h barriers + grid barrier ----------
constexpr int S_HALVES = 64 * 128;            // 16 KB per operand per stage
constexpr int STAGE_HALVES = 2 * S_HALVES;    // h + W
constexpr int SCLD = 68;
constexpr int SMEM_PERS = 4 * STAGE_HALVES * 2 + 64 * SCLD * 4;   // 131072 + 17408
constexpr int HBUF = 16 * 64 * 128;
constexpr int NCTA = 128;

DEV_INLINE int swaddr(int r, int cb, int tig) {   // uint32 index in 64x128-half block
    return r * 64 + ((cb ^ (r & 7)) << 2) + tig;
}

__global__ void __launch_bounds__(256, 1)
lstm_persist_kernel(const __half* __restrict__ Wblk, __half* __restrict__ hblk,
                    const __half* __restrict__ xg,
                    float* __restrict__ chist, float* __restrict__ hhist,
                    unsigned* __restrict__ barctr) {
    constexpr int NI = 4;
    extern __shared__ __half smem_s[];
    __shared__ __align__(8) uint64_t sbW[4], sbH[4];
    __shared__ float sc_c[1024];

    const int tid = threadIdx.x, wid = tid >> 5, lane = tid & 31;
    const int wrow = wid >> 1, wcol = wid & 1;   // 4 x 2 warps
    const int gl = lane >> 2, tig = lane & 3;
    const int tile = blockIdx.x, bn = tile * 64;
    float* sC = reinterpret_cast<float*>(smem_s + 4 * STAGE_HALVES);

    if (tid == 0) {
#pragma unroll
        for (int s = 0; s < 4; s++) { mbar_init(s2u(&sbW[s]), 1); mbar_init(s2u(&sbH[s]), 1); }
    }
    __syncthreads();

    const uint32_t smem0 = s2u(smem_s);
    auto issueW = [&](int kt, int stg) {
        mbar_expect_tx(s2u(&sbW[stg]), S_HALVES * 2);
        bulk_cp(smem0 + (stg * STAGE_HALVES + S_HALVES) * 2,
                Wblk + ((size_t)tile * 16 + kt) * S_HALVES, S_HALVES * 2, s2u(&sbW[stg]));
    };
    auto issueH = [&](int par, int kt, int stg) {
        mbar_expect_tx(s2u(&sbH[stg]), S_HALVES * 2);
        bulk_cp(smem0 + stg * STAGE_HALVES * 2,
                hblk + (size_t)par * HBUF + (size_t)kt * S_HALVES, S_HALVES * 2, s2u(&sbH[stg]));
    };

    int phW[4] = {0, 0, 0, 0}, phH[4] = {0, 0, 0, 0};

    for (int t = 0; t < Tt; t++) {
        float acc[NI][4];
#pragma unroll
        for (int ni = 0; ni < NI; ni++)
#pragma unroll
            for (int q = 0; q < 4; q++) acc[ni][q] = 0.0f;

        if (t > 0) {
            const int par = (t - 1) & 1;
            for (int q = 0; q < 4; q++) {
#pragma unroll
                for (int s = 0; s < 4; s++) {
                    const int kt = q * 4 + s;
                    __syncthreads();                 // readers of stage (s+3)&3 done
                    if (tid == 0) {
                        const int nk = kt + 3;
                        const int ns = (s + 3) & 3;
                        if (nk < 16) { issueW(nk, ns); issueH(par, nk, ns); }
                        else if (t < Tt - 1) issueW(nk - 16, ns);
                    }
                    mbar_wait(s2u(&sbW[s]), phW[s]); phW[s] ^= 1;
                    mbar_wait(s2u(&sbH[s]), phH[s]); phH[s] ^= 1;

                    const uint32_t* A32 = reinterpret_cast<const uint32_t*>(smem_s + s * STAGE_HALVES);
                    const uint32_t* B32 = A32 + S_HALVES / 2;
#pragma unroll
                    for (int ks = 0; ks < 8; ks++) {
                        uint32_t ah[4];
                        {
                            int r = wrow * 16 + gl;
                            ah[0] = A32[swaddr(r,     2 * ks,     tig)];
                            ah[1] = A32[swaddr(r + 8, 2 * ks,     tig)];
                            ah[2] = A32[swaddr(r,     2 * ks + 1, tig)];
                            ah[3] = A32[swaddr(r + 8, 2 * ks + 1, tig)];
                        }
#pragma unroll
                        for (int ni = 0; ni < NI; ni++) {
                            int r = wcol * 32 + ni * 8 + gl;
                            uint32_t bh[2] = {B32[swaddr(r, 2 * ks, tig)], B32[swaddr(r, 2 * ks + 1, tig)]};
                            mma16816h(acc[ni], ah, bh);
                        }
                    }
                }
            }
        } else {
            if (tid == 0) { issueW(0, 0); issueW(1, 1); issueW(2, 2); }
        }
        __syncthreads();

        // stage gates = acc + xg into separate sC region
        const __half* xg_t = xg + (size_t)t * Bb * Gg;
        {
            int r0 = wrow * 16 + gl, r1 = r0 + 8;
#pragma unroll
            for (int ni = 0; ni < NI; ni++) {
                int cb = wcol * 32 + ni * 8 + 2 * tig;
                float2 x0 = __half22float2(*reinterpret_cast<const __half2*>(xg_t + (size_t)r0 * Gg + bn + cb));
                float2 x1 = __half22float2(*reinterpret_cast<const __half2*>(xg_t + (size_t)r1 * Gg + bn + cb));
                sC[r0 * SCLD + cb]     = acc[ni][0] + x0.x;
                sC[r0 * SCLD + cb + 1] = acc[ni][1] + x0.y;
                sC[r1 * SCLD + cb]     = acc[ni][2] + x1.x;
                sC[r1 * SCLD + cb + 1] = acc[ni][3] + x1.y;
            }
        }
        __syncthreads();

        // LSTM elementwise; c persistent in smem
        __half* hbw = hblk + (size_t)(t & 1) * HBUF;
        float* cht = chist + (size_t)t * Bb * Hh;
        float* hht = hhist + (size_t)t * Bb * Hh;
#pragma unroll
        for (int it = 0; it < 4; it++) {
            int pair = it * 256 + tid;
            int b = pair >> 4, qq = pair & 15;
            int jg = (bn >> 2) + qq;
            float gi = sC[b * SCLD + 4 * qq + 0];
            float gf = sC[b * SCLD + 4 * qq + 1];
            float gg = sC[b * SCLD + 4 * qq + 2];
            float go = sC[b * SCLD + 4 * qq + 3];
            float cp = (t == 0) ? 0.0f : sc_c[pair];
            float si = 1.0f / (1.0f + expf(-gi));
            float sf = 1.0f / (1.0f + expf(-gf));
            float so = 1.0f / (1.0f + expf(-go));
            float cn = sf * cp + si * tanhf(gg);
            float hn = so * tanhf(cn);
            sc_c[pair] = cn;
            cht[b * Hh + jg] = cn;
            hht[b * Hh + jg] = hn;
            int kt = jg >> 7, ch = jg & 127, chunk = ch >> 3;
            hbw[((size_t)kt * 64 + b) * 128 + ((chunk ^ (b & 7)) << 3) + (ch & 7)] = __float2half(hn);
        }

        if (t < Tt - 1) {
            __threadfence();
            __syncthreads();
            if (tid == 0) {
                atomicAdd(barctr, 1u);
                unsigned target = (unsigned)NCTA * (unsigned)(t + 1);
                unsigned v;
                do {
                    asm volatile("ld.global.acquire.gpu.u32 %0, [%1];" : "=r"(v) : "l"(barctr));
                    if (v < target) __nanosleep(32);
                } while (v < target);
                __threadfence();
                issueH(t & 1, 0, 0); issueH(t & 1, 1, 1); issueH(t & 1, 2, 2);
            }
            __syncthreads();
        }
    }
}

// ---------- batched projections + gumbel softmax ----------
__global__ void __launch_bounds__(256, 1)
proj_kernel(const float* __restrict__ hhist, const float* __restrict__ chist,
            const float* __restrict__ Wpred, const float* __restrict__ bpred,
            const float* __restrict__ Wpredc, const float* __restrict__ bpredc,
            const float* __restrict__ Wutil, const float* __restrict__ butil,
            const float* __restrict__ Wuse, const float* __restrict__ buse,
            const float* __restrict__ gum, float* __restrict__ out) {
    const int tb = blockIdx.x;
    const int t = tb >> 6;
    const int tid = threadIdx.x;
    const float* hr = hhist + (size_t)tb * Hh;
    const float* cr = chist + (size_t)tb * Hh;
    float v[7] = {0, 0, 0, 0, 0, 0, 0};

    for (int j = tid; j < Hh; j += 256) {
        float hn = hr[j], cn = cr[j];
        v[0] += hn * Wpred[j];       v[1] += hn * Wpred[Hh + j];
        v[2] += cn * Wpredc[j];      v[3] += cn * Wpredc[Hh + j];
        v[4] += hn * Wutil[j];
        v[5] += hn * Wuse[j];        v[6] += hn * Wuse[Hh + j];
    }
#pragma unroll
    for (int o = 16; o > 0; o >>= 1)
#pragma unroll
        for (int q = 0; q < 7; q++) v[q] += __shfl_xor_sync(0xffffffffu, v[q], o);

    __shared__ float red[8][7];
    int wid = tid >> 5, lane = tid & 31;
    if (lane == 0)
#pragma unroll
        for (int q = 0; q < 7; q++) red[wid][q] = v[q];
    __syncthreads();

    if (tid == 0) {
        float s[7];
#pragma unroll
        for (int q = 0; q < 7; q++) {
            float a = 0;
#pragma unroll
            for (int w = 0; w < 8; w++) a += red[w][q];
            s[q] = a;
        }
        out[OUT_H + tb * 2 + 0] = s[0] + bpred[0];
        out[OUT_H + tb * 2 + 1] = s[1] + bpred[1];
        out[OUT_C + tb * 2 + 0] = s[2] + bpredc[0];
        out[OUT_C + tb * 2 + 1] = s[3] + bpredc[1];
        out[OUT_U + tb] = s[4] + butil[0];
        float z0 = s[5] + buse[0] + gum[tb * 2 + 0];
        float z1 = s[6] + buse[1] + gum[tb * 2 + 1];
        float mz = fmaxf(z0, z1);
        float e0 = expf(z0 - mz), e1 = expf(z1 - mz);
        float inv = 1.0f / (e0 + e1);
        if (t >= 1) {
            int b = tb & 63;
            out[OUT_W + ((t - 1) * Bb + b) * 2 + 0] = e0 * inv;
            out[OUT_W + ((t - 1) * Bb + b) * 2 + 1] = e1 * inv;
        }
    }
}

// ---------- launch ----------
extern "C" void kernel_launch(void* const* d_in, const int* in_sizes, int n_in,
                              void* d_out, int out_size) {
    const float* feature = (const float*)d_in[0];
    const float* W_ih    = (const float*)d_in[1];
    const float* W_hh    = (const float*)d_in[2];
    const float* b_ih    = (const float*)d_in[3];
    const float* b_hh    = (const float*)d_in[4];
    const float* W_pred  = (const float*)d_in[5];
    const float* b_pred  = (const float*)d_in[6];
    const float* W_predc = (const float*)d_in[7];
    const float* b_predc = (const float*)d_in[8];
    const float* W_util  = (const float*)d_in[9];
    const float* b_util  = (const float*)d_in[10];
    const float* W_use   = (const float*)d_in[11];
    const float* b_use   = (const float*)d_in[12];
    float* out = (float*)d_out;

    void *p_f, *p_wih, *p_whh, *p_xg, *p_ch, *p_hh, *p_h16, *p_gum, *p_bias, *p_bar;
    cudaGetSymbolAddress(&p_f, g_featT);
    cudaGetSymbolAddress(&p_wih, g_wih);   cudaGetSymbolAddress(&p_whh, g_whh_blk);
    cudaGetSymbolAddress(&p_xg, g_xg);
    cudaGetSymbolAddress(&p_ch, g_chist);  cudaGetSymbolAddress(&p_hh, g_hhist);
    cudaGetSymbolAddress(&p_h16, g_h16blk);
    cudaGetSymbolAddress(&p_gum, g_gumbel); cudaGetSymbolAddress(&p_bias, g_bias);
    cudaGetSymbolAddress(&p_bar, g_barctr);

    constexpr int SMEM_BIG = 4 * (128 * 72 + 128 * 72) * 2;   // 147456
    cudaFuncSetAttribute((const void*)gemm_pipe_kernel<128,128,64,4,2,4,64,32>,
                         cudaFuncAttributeMaxDynamicSharedMemorySize, SMEM_BIG);
    cudaFuncSetAttribute((const void*)lstm_persist_kernel,
                         cudaFuncAttributeMaxDynamicSharedMemorySize, SMEM_PERS);

    gumbel_kernel<<<49, 256>>>((float*)p_gum, (unsigned*)p_bar);
    bias_perm_kernel<<<(Gg + 255) / 256, 256>>>(b_ih, b_hh, (float*)p_bias);
    perm_h16_kernel<<<(Gg * Ff / 4 + 255) / 256, 256>>>(W_ih, (__half*)p_wih, Ff);
    perm_whh_blk_kernel<<<(128 * 16 * 64 * 16 + 255) / 256, 256>>>(W_hh, (__half*)p_whh);
    feat_prep_kernel<<<(M1 * Ff / 4 + 255) / 256, 256>>>(feature, (__half*)p_f);

    // xg = featT @ Wih_perm^T + bias_perm (permuted gate columns, fp16)
    gemm_pipe_kernel<128,128,64,4,2,4,64,32><<<dim3(Gg / 128, M1 / 128), 256, SMEM_BIG>>>(
        (const __half*)p_f, (const __half*)p_wih,
        (const float*)p_bias, (__half*)p_xg, Gg, Ff);

    lstm_persist_kernel<<<NCTA, 256, SMEM_PERS>>>(
        (const __half*)p_whh, (__half*)p_h16, (const __half*)p_xg,
        (float*)p_ch, (float*)p_hh, (unsigned*)p_bar);

    proj_kernel<<<M1, 256>>>((const float*)p_hh, (const float*)p_ch,
                             W_pred, b_pred, W_predc, b_predc,
                             W_util, b_util, W_use, b_use,
                             (const float*)p_gum, out);
}